// round 14
// baseline (speedup 1.0000x reference)
#include <cuda_runtime.h>
#include <cuda_fp16.h>
#include <cstdint>

// Problem constants
#define Bz   16
#define Ss   1024
#define Ls   512
#define Dd   1024
#define Hh   8
#define DHd  128
#define WDd  256
#define VOCP 1024
#define VOCR 1000
#define BLn  (Bz*Ls)      // 8192
#define BSn  (Bz*Ss)      // 16384
#define KFn  (Dd+WDd)     // 1280
#define T1c  (BLn*Dd)
#define T2c  (Bz*(Ls+1)*Dd)
#define BKT  64

// Scratch (static device globals — allocation-free per harness rules)
__device__ __align__(128) __half g_ENCh[BSn*Dd];
__device__ __align__(128) __half g_WQh [Dd*Dd];
__device__ __align__(128) __half g_WKh [Dd*Dd];
__device__ __align__(128) __half g_WVh [Dd*Dd];
__device__ __align__(128) __half g_WOh [Dd*Dd];
__device__ __align__(128) __half g_WOTh[Dd*Dd];       // Wo^T fp16
__device__ __align__(128) __half g_WPh [Dd*KFn];
__device__ __align__(128) __half g_Wch [Dd*Dd];       // Wp[:, :1024] @ Wo  (fp16)
__device__ __align__(128) __half g_TEh [VOCP*WDd];
__device__ __align__(128) float  g_PE  [VOCP*Dd];     // type_emb @ Wp[:,1024:]^T
__device__ __align__(128) float  g_bc  [Dd];          // Wp1·bo + b_proj (fp32 exact)
__device__ __align__(128) float  g_zeros[Dd];         // zero-initialized
__device__ __align__(128) __half g_Qh  [BLn*Dd];
__device__ __align__(128) __half g_Kh  [BSn*Dd];
__device__ __align__(128) __half g_Vh  [BSn*Dd];
__device__ __align__(128) __half g_CTXh[BLn*Dd];
__device__ __align__(128) float  g_EMB [BLn*Dd];
__device__ int            g_bcnt[BLn];
__device__ unsigned short g_bkt [BLn*BKT];
__device__ int g_is64;

// ---------------------------------------------------------------------------
__device__ __forceinline__ uint32_t smem_u32(const void* p) {
    uint32_t a;
    asm("{ .reg .u64 t; cvta.to.shared.u64 t, %1; cvt.u32.u64 %0, t; }" : "=r"(a) : "l"(p));
    return a;
}

__device__ __forceinline__ void cp16(uint32_t dst, const void* src) {
    asm volatile("cp.async.cg.shared.global [%0], [%1], 16;" :: "r"(dst), "l"(src));
}
#define CP_COMMIT() asm volatile("cp.async.commit_group;" ::: "memory")
#define CP_WAIT(n)  asm volatile("cp.async.wait_group %0;" :: "n"(n) : "memory")

#define LDSM4(r, addr) \
    asm volatile("ldmatrix.sync.aligned.m8n8.x4.shared.b16 {%0,%1,%2,%3}, [%4];" \
        : "=r"((r)[0]), "=r"((r)[1]), "=r"((r)[2]), "=r"((r)[3]) : "r"(addr))

#define MMA16816(c, a, b0, b1) \
    asm volatile("mma.sync.aligned.m16n8k16.row.col.f32.f16.f16.f32 " \
        "{%0,%1,%2,%3}, {%4,%5,%6,%7}, {%8,%9}, {%0,%1,%2,%3};" \
        : "+f"((c)[0]), "+f"((c)[1]), "+f"((c)[2]), "+f"((c)[3]) \
        : "r"((a)[0]), "r"((a)[1]), "r"((a)[2]), "r"((a)[3]), "r"(b0), "r"(b1))

#define STG_B 32768
#define SM_TOT (3*STG_B)

__device__ __forceinline__ int load_idx_i(const void* p, int i, int is64) {
    return is64 ? (int)((const long long*)p)[i] : ((const int*)p)[i];
}

// ---------------------------------------------------------------------------
// GEMM core (NT): acc += A[bm:bm+128, :K] * W[bn:bn+128, :K]^T
// 128x128 CTA tile, 256 threads, 8 warps of 32x64, BK=64, 3-stage cp.async.
__device__ __forceinline__ void gemm_tile_core(
    float acc[2][8][4],
    const __half* __restrict__ Ab, int lda,
    const __half* __restrict__ Wb, int ldw,
    int KT, uint32_t sb, int tid,
    int gmode, const void* __restrict__ ts, int gbm, int is64)
{
    const int warp = tid >> 5, lane = tid & 31;
    const int wm = warp & 3, wn = warp >> 2;

    const __half* aptr[4];
    const __half* wptr[4];
    uint32_t soff[4];
    #pragma unroll
    for (int i = 0; i < 4; i++) {
        int c = tid + i * 256;
        int row = c >> 3, ch = c & 7;
        soff[i] = (uint32_t)((row << 7) + ((ch << 4) ^ ((row & 7) << 4)));
        if (gmode) {
            int m = gbm + row;
            int idx = load_idx_i(ts, m, is64);
            aptr[i] = Ab + (((size_t)(m >> 9) << 10) + (size_t)idx) * Dd + ch * 8;
        } else {
            aptr[i] = Ab + (size_t)row * lda + ch * 8;
        }
        wptr[i] = Wb + (size_t)row * ldw + ch * 8;
    }

    auto load = [&](int stage, int kt) {
        const int k0 = kt * 64;
        uint32_t sa = sb + stage * STG_B;
        uint32_t sw = sa + 16384;
        #pragma unroll
        for (int i = 0; i < 4; i++) {
            cp16(sa + soff[i], aptr[i] + k0);
            cp16(sw + soff[i], wptr[i] + k0);
        }
        CP_COMMIT();
    };

    load(0, 0);
    load(1, 1);

    const int rlA = (lane & 7) + ((lane >> 3) & 1) * 8;
    const int caA = ((lane >> 4) & 1) << 4;
    const int rlB = (lane & 7) + ((lane >> 4) & 1) * 8;
    const int caB = ((lane >> 3) & 1) << 4;
    const uint32_t swA = (uint32_t)(rlA & 7) << 4;
    const uint32_t swB = (uint32_t)(rlB & 7) << 4;
    const uint32_t rowA0 = (uint32_t)((wm * 32 +  0 + rlA) << 7);
    const uint32_t rowA1 = (uint32_t)((wm * 32 + 16 + rlA) << 7);
    const uint32_t rowB0 = (uint32_t)((wn * 64 +  0 + rlB) << 7);
    const uint32_t rowB1 = (uint32_t)((wn * 64 + 16 + rlB) << 7);
    const uint32_t rowB2 = (uint32_t)((wn * 64 + 32 + rlB) << 7);
    const uint32_t rowB3 = (uint32_t)((wn * 64 + 48 + rlB) << 7);

    for (int kt = 0; kt < KT; kt++) {
        if (kt + 2 < KT) { CP_WAIT(1); } else { CP_WAIT(0); }
        __syncthreads();
        if (kt + 2 < KT) load((kt + 2) % 3, kt + 2);

        uint32_t ab = sb + (kt % 3) * STG_B;
        uint32_t bb = ab + 16384;

        #pragma unroll
        for (int q = 0; q < 4; q++) {
            const uint32_t cA = (uint32_t)((q << 5) + caA) ^ swA;
            const uint32_t cB = (uint32_t)((q << 5) + caB) ^ swB;
            uint32_t a[2][4], b[4][4];
            LDSM4(a[0], ab + rowA0 + cA);
            LDSM4(a[1], ab + rowA1 + cA);
            LDSM4(b[0], bb + rowB0 + cB);
            LDSM4(b[1], bb + rowB1 + cB);
            LDSM4(b[2], bb + rowB2 + cB);
            LDSM4(b[3], bb + rowB3 + cB);
            #pragma unroll
            for (int mt = 0; mt < 2; mt++)
                #pragma unroll
                for (int np = 0; np < 4; np++) {
                    MMA16816(acc[mt][2*np],     a[mt], b[np][0], b[np][1]);
                    MMA16816(acc[mt][2*np + 1], a[mt], b[np][2], b[np][3]);
                }
        }
    }
}

// fp16 epilogue
__device__ __forceinline__ void epi_half(
    float acc[2][8][4], const float* __restrict__ bias, float alpha,
    __half* __restrict__ C, int ldc, int bm, int bn, int tid)
{
    const int warp = tid >> 5, lane = tid & 31;
    const int wm = warp & 3, wn = warp >> 2;
    const int g = lane >> 2, t2 = (lane & 3) * 2;
    #pragma unroll
    for (int nt = 0; nt < 8; nt++) {
        int c0 = bn + wn * 64 + nt * 8 + t2;
        float2 bv = *(const float2*)(bias + c0);
        #pragma unroll
        for (int mt = 0; mt < 2; mt++) {
            int r0 = bm + wm * 32 + mt * 16 + g;
            *(__half2*)(C + (size_t)r0 * ldc + c0) =
                __floats2half2_rn(alpha * (acc[mt][nt][0] + bv.x),
                                  alpha * (acc[mt][nt][1] + bv.y));
            *(__half2*)(C + (size_t)(r0 + 8) * ldc + c0) =
                __floats2half2_rn(alpha * (acc[mt][nt][2] + bv.x),
                                  alpha * (acc[mt][nt][3] + bv.y));
        }
    }
}

// ---------------------------------------------------------------------------
// fused Q + K + V projections; Q segment gathers its A rows via to_sem
__global__ __launch_bounds__(256, 2) void qkv_gemm(
    const float* __restrict__ bq, const float* __restrict__ bk,
    const float* __restrict__ bv, float qscale,
    const void* __restrict__ to_sem)
{
    extern __shared__ char smem[];
    const uint32_t sb = smem_u32(smem);
    const int tid = threadIdx.x;
    const int is64 = g_is64;
    int id = blockIdx.x;

    const __half* W; const float* bias; __half* C;
    float alpha; int bm, bn, gmode;
    if (id < 512) {
        W = g_WQh; bias = bq; C = g_Qh; alpha = qscale; gmode = 1;
        bm = (id >> 3) * 128; bn = (id & 7) * 128;
    } else if (id < 1536) {
        int t = id - 512;
        W = g_WKh; bias = bk; C = g_Kh; alpha = 1.0f; gmode = 0;
        bm = (t >> 3) * 128; bn = (t & 7) * 128;
    } else {
        int t = id - 1536;
        W = g_WVh; bias = bv; C = g_Vh; alpha = 1.0f; gmode = 0;
        bm = (t >> 3) * 128; bn = (t & 7) * 128;
    }

    float acc[2][8][4];
    #pragma unroll
    for (int i = 0; i < 2; i++)
        #pragma unroll
        for (int j = 0; j < 8; j++)
            #pragma unroll
            for (int r = 0; r < 4; r++) acc[i][j][r] = 0.f;

    const __half* Ab = gmode ? g_ENCh : (g_ENCh + (size_t)bm * Dd);
    gemm_tile_core(acc, Ab, Dd, W + (size_t)bn * Dd, Dd, 16, sb, tid,
                   gmode, to_sem, bm, is64);
    epi_half(acc, bias, alpha, C, Dd, bm, bn, tid);
}

// Wc precompute: Wc[n,i] = sum_j Wp[n,j]*Wo[j,i]  (A=WPh ld KFn, W=WOTh ld Dd)
__global__ __launch_bounds__(256, 2) void wc_gemm() {
    extern __shared__ char smem[];
    const uint32_t sb = smem_u32(smem);
    const int tid = threadIdx.x;
    int id = blockIdx.x;
    int bm = (id >> 3) * 128, bn = (id & 7) * 128;

    float acc[2][8][4];
    #pragma unroll
    for (int i = 0; i < 2; i++)
        #pragma unroll
        for (int j = 0; j < 8; j++)
            #pragma unroll
            for (int r = 0; r < 4; r++) acc[i][j][r] = 0.f;

    gemm_tile_core(acc, g_WPh + (size_t)bm * KFn, KFn, g_WOTh + (size_t)bn * Dd, Dd,
                   16, sb, tid, 0, nullptr, 0, 0);
    epi_half(acc, g_zeros, 1.0f, g_Wch, Dd, bm, bn, tid);
}

// PE precompute: PE[t][n] = sum_k TEh[t][k] * WPh[n][1024+k]  (K=256)
__global__ __launch_bounds__(256, 2) void pe_gemm() {
    extern __shared__ char smem[];
    const uint32_t sb = smem_u32(smem);
    const int tid = threadIdx.x;
    int id = blockIdx.x;
    int bm = (id >> 3) * 128, bn = (id & 7) * 128;

    float acc[2][8][4];
    #pragma unroll
    for (int i = 0; i < 2; i++)
        #pragma unroll
        for (int j = 0; j < 8; j++)
            #pragma unroll
            for (int r = 0; r < 4; r++) acc[i][j][r] = 0.f;

    gemm_tile_core(acc, g_TEh + (size_t)bm * WDd, WDd,
                   g_WPh + (size_t)bn * KFn + Dd, KFn, 4, sb, tid, 0, nullptr, 0, 0);

    const int warp = tid >> 5, lane = tid & 31;
    const int wm = warp & 3, wn = warp >> 2;
    const int g = lane >> 2, t2 = (lane & 3) * 2;
    #pragma unroll
    for (int nt = 0; nt < 8; nt++) {
        int c0 = bn + wn * 64 + nt * 8 + t2;
        #pragma unroll
        for (int mt = 0; mt < 2; mt++) {
            int r0 = bm + wm * 32 + mt * 16 + g;
            float2 o0 = {acc[mt][nt][0], acc[mt][nt][1]};
            float2 o1 = {acc[mt][nt][2], acc[mt][nt][3]};
            *(float2*)(g_PE + (size_t)r0 * Dd + c0)       = o0;
            *(float2*)(g_PE + (size_t)(r0 + 8) * Dd + c0) = o1;
        }
    }
}

// combined projection: emb = CTXh @ Wch^T + bc + PE[tt]; dual store / EMB
__global__ __launch_bounds__(256, 2) void c_gemm(const void* __restrict__ tt,
                                                 float* __restrict__ out, int direct) {
    extern __shared__ char smem[];
    const uint32_t sb = smem_u32(smem);
    const int tid = threadIdx.x;
    int id = blockIdx.x;
    int bm = (id >> 3) * 128, bn = (id & 7) * 128;

    float acc[2][8][4];
    #pragma unroll
    for (int i = 0; i < 2; i++)
        #pragma unroll
        for (int j = 0; j < 8; j++)
            #pragma unroll
            for (int r = 0; r < 4; r++) acc[i][j][r] = 0.f;

    gemm_tile_core(acc, g_CTXh + (size_t)bm * Dd, Dd, g_Wch + (size_t)bn * Dd, Dd,
                   16, sb, tid, 0, nullptr, 0, 0);

    const int warp = tid >> 5, lane = tid & 31;
    const int wm = warp & 3, wn = warp >> 2;
    const int g = lane >> 2, t2 = (lane & 3) * 2;
    const int is64 = g_is64;

    int rows[2][2];
    const float* pe[2][2];
    #pragma unroll
    for (int mt = 0; mt < 2; mt++) {
        int r0 = bm + wm * 32 + mt * 16 + g;
        rows[mt][0] = r0;
        rows[mt][1] = r0 + 8;
        pe[mt][0] = g_PE + (size_t)load_idx_i(tt, r0,     is64) * Dd;
        pe[mt][1] = g_PE + (size_t)load_idx_i(tt, r0 + 8, is64) * Dd;
    }

    #pragma unroll
    for (int nt = 0; nt < 8; nt++) {
        int c0 = bn + wn * 64 + nt * 8 + t2;
        float2 bv = *(const float2*)(g_bc + c0);
        #pragma unroll
        for (int mt = 0; mt < 2; mt++) {
            float2 pa = *(const float2*)(pe[mt][0] + c0);
            float2 pb = *(const float2*)(pe[mt][1] + c0);
            int r0 = rows[mt][0], rb = rows[mt][1];
            float2 o0 = {acc[mt][nt][0] + bv.x + pa.x, acc[mt][nt][1] + bv.y + pa.y};
            float2 o1 = {acc[mt][nt][2] + bv.x + pb.x, acc[mt][nt][3] + bv.y + pb.y};
            if (direct) {
                int b0 = r0 >> 9, l0 = r0 & 511;
                int b1 = rb >> 9, l1 = rb & 511;
                *(float2*)(out + (size_t)r0 * Dd + c0) = o0;
                *(float2*)(out + (size_t)rb * Dd + c0) = o1;
                *(float2*)(out + T1c + ((size_t)b0 * (Ls+1) + l0 + 1) * Dd + c0) = o0;
                *(float2*)(out + T1c + ((size_t)b1 * (Ls+1) + l1 + 1) * Dd + c0) = o1;
            } else {
                *(float2*)(g_EMB + (size_t)r0 * Dd + c0) = o0;
                *(float2*)(g_EMB + (size_t)rb * Dd + c0) = o1;
            }
        }
    }
}

// ---------------------------------------------------------------------------
// fp32 -> fp16 conversions (7 segs) + dtype detect (seg 7)
__global__ void f2h_all(const float* __restrict__ e, const float* __restrict__ q,
                        const float* __restrict__ k, const float* __restrict__ v,
                        const float* __restrict__ o, const float* __restrict__ p,
                        const float* __restrict__ te,
                        const void* __restrict__ to_sem) {
    int seg = blockIdx.y;
    if (seg == 7) {
        __shared__ int nz;
        if (threadIdx.x == 0) nz = 0;
        __syncthreads();
        if (blockIdx.x == 0) {
            const int* qw = (const int*)to_sem;
            int bad = 0;
            for (int i = threadIdx.x * 2 + 1; i < 8192; i += 2 * blockDim.x)
                if (qw[i] != 0) bad = 1;
            if (bad) atomicAdd(&nz, 1);
            __syncthreads();
            if (threadIdx.x == 0) g_is64 = (nz == 0) ? 1 : 0;
        }
        return;
    }
    const float* srcs[7] = {e, q, k, v, o, p, te};
    __half* dsts[7] = {g_ENCh, g_WQh, g_WKh, g_WVh, g_WOh, g_WPh, g_TEh};
    const int n8s[7] = {BSn*Dd/8, Dd*Dd/8, Dd*Dd/8, Dd*Dd/8, Dd*Dd/8, Dd*KFn/8,
                        VOCP*WDd/8};
    const int vr8 = VOCR*WDd/8;
    const float* src = srcs[seg];
    __half* dst = dsts[seg];
    int n8 = n8s[seg];
    for (int i = blockIdx.x * blockDim.x + threadIdx.x; i < n8;
         i += gridDim.x * blockDim.x) {
        float4 a, b;
        if (seg == 6 && i >= vr8) {
            a = make_float4(0.f, 0.f, 0.f, 0.f);
            b = a;
        } else {
            a = ((const float4*)src)[2*i];
            b = ((const float4*)src)[2*i+1];
        }
        __half2 h[4];
        h[0] = __floats2half2_rn(a.x, a.y);
        h[1] = __floats2half2_rn(a.z, a.w);
        h[2] = __floats2half2_rn(b.x, b.y);
        h[3] = __floats2half2_rn(b.z, b.w);
        ((float4*)dst)[i] = *(float4*)h;
    }
}

// Wo transpose (fp32 source -> fp16 WOT), smem-tiled
__global__ void transpose_wo(const float* __restrict__ wo) {
    __shared__ float t[32][33];
    int bx = blockIdx.x * 32, by = blockIdx.y * 32;
    int x = threadIdx.x, y0 = threadIdx.y;
    #pragma unroll
    for (int dy = 0; dy < 32; dy += 8)
        t[y0 + dy][x] = wo[(size_t)(by + y0 + dy) * Dd + bx + x];
    __syncthreads();
    #pragma unroll
    for (int dy = 0; dy < 32; dy += 8) {
        int i = bx + y0 + dy;
        int j = by + x;
        g_WOTh[(size_t)i * Dd + j] = __float2half(t[x][y0 + dy]);
    }
}

// bc = Wp1·bo + b_proj (fp32 exact); one thread per output
__global__ void bc_kernel(const float* __restrict__ wp, const float* __restrict__ bo,
                          const float* __restrict__ bp) {
    int n = blockIdx.x * blockDim.x + threadIdx.x;
    if (n >= Dd) return;
    const float* row = wp + (size_t)n * KFn;
    float s = bp[n];
    for (int k = 0; k < Dd; k++) s += row[k] * bo[k];
    g_bc[n] = s;
}

// ---------------------------------------------------------------------------
// bucket build (blocks 0..15) + root rows of d_out (blocks 16..31)
__global__ __launch_bounds__(1024) void build_buckets(const void* __restrict__ sem_syn,
                                                      const float* __restrict__ root,
                                                      float* __restrict__ out,
                                                      int direct) {
    if (blockIdx.x >= Bz) {
        if (direct) {
            int b = blockIdx.x - Bz;
            if (threadIdx.x < 256)
                ((float4*)(out + (size_t)T1c + (size_t)b * (Ls + 1) * Dd))[threadIdx.x] =
                    ((const float4*)root)[threadIdx.x];
        }
        return;
    }
    int b = blockIdx.x;
    int j = threadIdx.x;
    const int is64 = g_is64;
    if (j < Ls) g_bcnt[b * Ls + j] = 0;
    __syncthreads();
    long long v = is64 ? ((const long long*)sem_syn)[b * Ss + j]
                       : (long long)((const int*)sem_syn)[b * Ss + j];
    if (v >= 1 && v <= Ls) {
        int i = (int)v - 1;
        int slot = atomicAdd(&g_bcnt[b * Ls + i], 1);
        if (slot < BKT) g_bkt[(b * Ls + i) * BKT + slot] = (unsigned short)j;
    }
}

// ---------------------------------------------------------------------------
// Sparse masked attention using precomputed buckets; ~3KB smem.
__global__ __launch_bounds__(128) void attn_kernel(
    const void* __restrict__ to_sem, const void* __restrict__ sem_syn)
{
    int bl = blockIdx.x;
    int b = bl >> 9, i = bl & 511;
    int tid = threadIdx.x;

    __shared__ int   s_idx[BKT + 8];
    __shared__ float s_sc[Hh][BKT + 8];
    __shared__ int   s_total;

    const int is64 = g_is64;
    const int base = b * Ss;
    const long long target = (long long)(i + 1);

    int cnt = g_bcnt[bl];
    if (cnt > BKT) cnt = BKT;
    if (tid < cnt) s_idx[tid] = g_bkt[bl * BKT + tid];
    __syncthreads();

    if (tid == 0) {
        for (int x = 1; x < cnt; x++) {
            int key = s_idx[x];
            int y = x - 1;
            while (y >= 0 && s_idx[y] > key) { s_idx[y + 1] = s_idx[y]; y--; }
            s_idx[y + 1] = key;
        }
        int jself = load_idx_i(to_sem, bl, is64);
        long long vs = is64 ? ((const long long*)sem_syn)[base + jself]
                            : (long long)((const int*)sem_syn)[base + jself];
        int M = cnt;
        if (vs != target) { s_idx[M] = jself; M++; }
        s_total = M;
    }
    __syncthreads();
    const int M = s_total;

    int h = tid >> 4, l16 = tid & 15;
    float qr[8];
    {
        uint4 u = *(const uint4*)(g_Qh + (size_t)bl * Dd + h * DHd + l16 * 8);
        const __half2* hp = (const __half2*)&u;
        float2 f0 = __half22float2(hp[0]), f1 = __half22float2(hp[1]);
        float2 f2 = __half22float2(hp[2]), f3 = __half22float2(hp[3]);
        qr[0]=f0.x; qr[1]=f0.y; qr[2]=f1.x; qr[3]=f1.y;
        qr[4]=f2.x; qr[5]=f2.y; qr[6]=f3.x; qr[7]=f3.y;
    }

    for (int m = 0; m < M; m++) {
        int j = s_idx[m];
        uint4 u = *(const uint4*)(g_Kh + (size_t)(base + j) * Dd + h * DHd + l16 * 8);
        const __half2* hp = (const __half2*)&u;
        float2 k0 = __half22float2(hp[0]), k1 = __half22float2(hp[1]);
        float2 k2 = __half22float2(hp[2]), k3 = __half22float2(hp[3]);
        float p = qr[0]*k0.x + qr[1]*k0.y + qr[2]*k1.x + qr[3]*k1.y
                + qr[4]*k2.x + qr[5]*k2.y + qr[6]*k3.x + qr[7]*k3.y;
        p += __shfl_xor_sync(0xffffffffu, p, 1);
        p += __shfl_xor_sync(0xffffffffu, p, 2);
        p += __shfl_xor_sync(0xffffffffu, p, 4);
        p += __shfl_xor_sync(0xffffffffu, p, 8);
        if (l16 == 0) s_sc[h][m] = p;
    }
    __syncthreads();

    float mx = -3.0e38f;
    for (int m = 0; m < M; m++) mx = fmaxf(mx, s_sc[h][m]);
    float den = 0.f;
    for (int m = 0; m < M; m++) den += expf(s_sc[h][m] - mx);

    float acc[8];
    #pragma unroll
    for (int c = 0; c < 8; c++) acc[c] = 0.f;
    for (int m = 0; m < M; m++) {
        float p = expf(s_sc[h][m] - mx);
        int j = s_idx[m];
        uint4 u = *(const uint4*)(g_Vh + (size_t)(base + j) * Dd + h * DHd + l16 * 8);
        const __half2* hp = (const __half2*)&u;
        float2 v0 = __half22float2(hp[0]), v1 = __half22float2(hp[1]);
        float2 v2 = __half22float2(hp[2]), v3 = __half22float2(hp[3]);
        acc[0] += p * v0.x; acc[1] += p * v0.y; acc[2] += p * v1.x; acc[3] += p * v1.y;
        acc[4] += p * v2.x; acc[5] += p * v2.y; acc[6] += p * v3.x; acc[7] += p * v3.y;
    }
    float inv = 1.0f / den;
    __half2 h0 = __floats2half2_rn(acc[0]*inv, acc[1]*inv);
    __half2 h1 = __floats2half2_rn(acc[2]*inv, acc[3]*inv);
    __half2 h2 = __floats2half2_rn(acc[4]*inv, acc[5]*inv);
    __half2 h3 = __floats2half2_rn(acc[6]*inv, acc[7]*inv);
    uint4 u = { *(uint32_t*)&h0, *(uint32_t*)&h1, *(uint32_t*)&h2, *(uint32_t*)&h3 };
    *(uint4*)(g_CTXh + (size_t)bl * Dd + h * DHd + l16 * 8) = u;
}

// ---------------------------------------------------------------------------
// fallback output packer (only used when out_size doesn't match full tuple)
__global__ void write_out(const float* __restrict__ root, float* __restrict__ out,
                          int out_size) {
    const int T1 = T1c, T2 = T2c;
    int base2, n;
    if (out_size >= T1 + T2)      { base2 = T1; n = T1 + T2; }
    else if (out_size == T2)      { base2 = 0;  n = T2; }
    else                          { base2 = -1; n = T1; }
    int n4 = n >> 2;
    for (int i4 = blockIdx.x * blockDim.x + threadIdx.x; i4 < n4;
         i4 += gridDim.x * blockDim.x) {
        int e = i4 << 2;
        float4 val;
        if (base2 >= 0 && e >= base2) {
            int off = e - base2;
            int b = off / ((Ls + 1) * Dd);
            int r = off - b * ((Ls + 1) * Dd);
            int l = r >> 10;
            int dd = r & (Dd - 1);
            if (l == 0)
                val = ((const float4*)root)[dd >> 2];
            else
                val = ((const float4*)(g_EMB + ((size_t)(b * Ls + l - 1) << 10)))[dd >> 2];
        } else {
            val = ((const float4*)g_EMB)[i4];
        }
        ((float4*)out)[i4] = val;
    }
}

// ---------------------------------------------------------------------------
extern "C" void kernel_launch(void* const* d_in, const int* in_sizes, int n_in,
                              void* d_out, int out_size) {
    const float* enc     = (const float*)d_in[0];
    const void*  to_sem  = d_in[1];
    const void*  tt      = d_in[2];
    const void*  sem_syn = d_in[3];
    const float* bq = (const float*)d_in[5];
    const float* bk = (const float*)d_in[7];
    const float* bv = (const float*)d_in[9];
    const float* wo = (const float*)d_in[10];
    const float* bo = (const float*)d_in[11];
    const float* type_emb = (const float*)d_in[12];
    const float* w_proj   = (const float*)d_in[13];
    const float* b_proj   = (const float*)d_in[14];
    const float* root     = (const float*)d_in[15];

    cudaFuncSetAttribute(qkv_gemm, cudaFuncAttributeMaxDynamicSharedMemorySize, SM_TOT);
    cudaFuncSetAttribute(wc_gemm,  cudaFuncAttributeMaxDynamicSharedMemorySize, SM_TOT);
    cudaFuncSetAttribute(pe_gemm,  cudaFuncAttributeMaxDynamicSharedMemorySize, SM_TOT);
    cudaFuncSetAttribute(c_gemm,   cudaFuncAttributeMaxDynamicSharedMemorySize, SM_TOT);

    const float qscale = 0.08838834764831843f;   // 1/sqrt(128)
    const int direct = (out_size >= T1c + T2c);

    // conversions + dtype detect
    f2h_all<<<dim3(1024, 8), 256>>>(enc, (const float*)d_in[4], (const float*)d_in[6],
                                    (const float*)d_in[8], wo,
                                    w_proj, type_emb, to_sem);
    // precomputes (off the qkv critical path)
    transpose_wo<<<dim3(32, 32), dim3(32, 8)>>>(wo);
    wc_gemm<<<64, 256, SM_TOT>>>();
    bc_kernel<<<8, 128>>>(w_proj, bo, b_proj);
    pe_gemm<<<64, 256, SM_TOT>>>();
    build_buckets<<<2 * Bz, 1024>>>(sem_syn, root, (float*)d_out, direct);

    qkv_gemm<<<2560, 256, SM_TOT>>>(bq, bk, bv, qscale, to_sem);

    attn_kernel<<<BLn, 128>>>(to_sem, sem_syn);

    // single combined projection replaces o_gemm + p_gemm
    c_gemm<<<512, 256, SM_TOT>>>(tt, (float*)d_out, direct);

    if (!direct) write_out<<<2048, 256>>>(root, (float*)d_out, out_size);
}

// round 15
// speedup vs baseline: 1.1796x; 1.1796x over previous
#include <cuda_runtime.h>
#include <cuda_fp16.h>
#include <cstdint>

// Problem constants
#define Bz   16
#define Ss   1024
#define Ls   512
#define Dd   1024
#define Hh   8
#define DHd  128
#define WDd  256
#define VOCP 1024
#define VOCR 1000
#define BLn  (Bz*Ls)      // 8192
#define BSn  (Bz*Ss)      // 16384
#define KFn  (Dd+WDd)     // 1280
#define T1c  (BLn*Dd)
#define T2c  (Bz*(Ls+1)*Dd)
#define BKT  64

// Scratch (static device globals — allocation-free per harness rules)
__device__ __align__(128) __half g_ENCh[BSn*Dd];
__device__ __align__(128) __half g_WQh [Dd*Dd];
__device__ __align__(128) __half g_WKh [Dd*Dd];
__device__ __align__(128) __half g_WVh [Dd*Dd];
__device__ __align__(128) __half g_WOh [Dd*Dd];
__device__ __align__(128) __half g_WOTh[Dd*Dd];       // Wo^T fp16
__device__ __align__(128) __half g_WPh [Dd*KFn];
__device__ __align__(128) __half g_Wch [Dd*Dd];       // Wp[:, :1024] @ Wo  (fp16)
__device__ __align__(128) __half g_TEh [VOCP*WDd];
__device__ __align__(128) float  g_PE  [VOCP*Dd];     // type_emb @ Wp[:,1024:]^T
__device__ __align__(128) float  g_bc  [Dd];          // Wp1·bo + b_proj (fp32 exact)
__device__ __align__(128) float  g_zeros[Dd];         // zero-initialized
__device__ __align__(128) __half g_Qh  [BLn*Dd];
__device__ __align__(128) __half g_Kh  [BSn*Dd];
__device__ __align__(128) __half g_Vh  [BSn*Dd];
__device__ __align__(128) __half g_CTXh[BLn*Dd];
__device__ __align__(128) float  g_EMB [BLn*Dd];
__device__ int            g_bcnt[BLn];
__device__ unsigned short g_bkt [BLn*BKT];
__device__ int g_is64;

// ---------------------------------------------------------------------------
__device__ __forceinline__ uint32_t smem_u32(const void* p) {
    uint32_t a;
    asm("{ .reg .u64 t; cvta.to.shared.u64 t, %1; cvt.u32.u64 %0, t; }" : "=r"(a) : "l"(p));
    return a;
}

__device__ __forceinline__ void cp16(uint32_t dst, const void* src) {
    asm volatile("cp.async.cg.shared.global [%0], [%1], 16;" :: "r"(dst), "l"(src));
}
#define CP_COMMIT() asm volatile("cp.async.commit_group;" ::: "memory")
#define CP_WAIT(n)  asm volatile("cp.async.wait_group %0;" :: "n"(n) : "memory")

#define LDSM4(r, addr) \
    asm volatile("ldmatrix.sync.aligned.m8n8.x4.shared.b16 {%0,%1,%2,%3}, [%4];" \
        : "=r"((r)[0]), "=r"((r)[1]), "=r"((r)[2]), "=r"((r)[3]) : "r"(addr))

#define MMA16816(c, a, b0, b1) \
    asm volatile("mma.sync.aligned.m16n8k16.row.col.f32.f16.f16.f32 " \
        "{%0,%1,%2,%3}, {%4,%5,%6,%7}, {%8,%9}, {%0,%1,%2,%3};" \
        : "+f"((c)[0]), "+f"((c)[1]), "+f"((c)[2]), "+f"((c)[3]) \
        : "r"((a)[0]), "r"((a)[1]), "r"((a)[2]), "r"((a)[3]), "r"(b0), "r"(b1))

#define STG_B 32768
#define SM_TOT (3*STG_B)

__device__ __forceinline__ int load_idx_i(const void* p, int i, int is64) {
    return is64 ? (int)((const long long*)p)[i] : ((const int*)p)[i];
}

// ---------------------------------------------------------------------------
// GEMM core (NT): acc += A[bm:bm+128, :K] * W[bn:bn+128, :K]^T
// 128x128 CTA tile, 256 threads, 8 warps of 32x64, BK=64, 3-stage cp.async.
__device__ __forceinline__ void gemm_tile_core(
    float acc[2][8][4],
    const __half* __restrict__ Ab, int lda,
    const __half* __restrict__ Wb, int ldw,
    int KT, uint32_t sb, int tid,
    int gmode, const void* __restrict__ ts, int gbm, int is64)
{
    const int warp = tid >> 5, lane = tid & 31;
    const int wm = warp & 3, wn = warp >> 2;

    const __half* aptr[4];
    const __half* wptr[4];
    uint32_t soff[4];
    #pragma unroll
    for (int i = 0; i < 4; i++) {
        int c = tid + i * 256;
        int row = c >> 3, ch = c & 7;
        soff[i] = (uint32_t)((row << 7) + ((ch << 4) ^ ((row & 7) << 4)));
        if (gmode) {
            int m = gbm + row;
            int idx = load_idx_i(ts, m, is64);
            aptr[i] = Ab + (((size_t)(m >> 9) << 10) + (size_t)idx) * Dd + ch * 8;
        } else {
            aptr[i] = Ab + (size_t)row * lda + ch * 8;
        }
        wptr[i] = Wb + (size_t)row * ldw + ch * 8;
    }

    auto load = [&](int stage, int kt) {
        const int k0 = kt * 64;
        uint32_t sa = sb + stage * STG_B;
        uint32_t sw = sa + 16384;
        #pragma unroll
        for (int i = 0; i < 4; i++) {
            cp16(sa + soff[i], aptr[i] + k0);
            cp16(sw + soff[i], wptr[i] + k0);
        }
        CP_COMMIT();
    };

    load(0, 0);
    load(1, 1);

    const int rlA = (lane & 7) + ((lane >> 3) & 1) * 8;
    const int caA = ((lane >> 4) & 1) << 4;
    const int rlB = (lane & 7) + ((lane >> 4) & 1) * 8;
    const int caB = ((lane >> 3) & 1) << 4;
    const uint32_t swA = (uint32_t)(rlA & 7) << 4;
    const uint32_t swB = (uint32_t)(rlB & 7) << 4;
    const uint32_t rowA0 = (uint32_t)((wm * 32 +  0 + rlA) << 7);
    const uint32_t rowA1 = (uint32_t)((wm * 32 + 16 + rlA) << 7);
    const uint32_t rowB0 = (uint32_t)((wn * 64 +  0 + rlB) << 7);
    const uint32_t rowB1 = (uint32_t)((wn * 64 + 16 + rlB) << 7);
    const uint32_t rowB2 = (uint32_t)((wn * 64 + 32 + rlB) << 7);
    const uint32_t rowB3 = (uint32_t)((wn * 64 + 48 + rlB) << 7);

    for (int kt = 0; kt < KT; kt++) {
        if (kt + 2 < KT) { CP_WAIT(1); } else { CP_WAIT(0); }
        __syncthreads();
        if (kt + 2 < KT) load((kt + 2) % 3, kt + 2);

        uint32_t ab = sb + (kt % 3) * STG_B;
        uint32_t bb = ab + 16384;

        #pragma unroll
        for (int q = 0; q < 4; q++) {
            const uint32_t cA = (uint32_t)((q << 5) + caA) ^ swA;
            const uint32_t cB = (uint32_t)((q << 5) + caB) ^ swB;
            uint32_t a[2][4], b[4][4];
            LDSM4(a[0], ab + rowA0 + cA);
            LDSM4(a[1], ab + rowA1 + cA);
            LDSM4(b[0], bb + rowB0 + cB);
            LDSM4(b[1], bb + rowB1 + cB);
            LDSM4(b[2], bb + rowB2 + cB);
            LDSM4(b[3], bb + rowB3 + cB);
            #pragma unroll
            for (int mt = 0; mt < 2; mt++)
                #pragma unroll
                for (int np = 0; np < 4; np++) {
                    MMA16816(acc[mt][2*np],     a[mt], b[np][0], b[np][1]);
                    MMA16816(acc[mt][2*np + 1], a[mt], b[np][2], b[np][3]);
                }
        }
    }
}

// fp16 epilogue
__device__ __forceinline__ void epi_half(
    float acc[2][8][4], const float* __restrict__ bias, float alpha,
    __half* __restrict__ C, int ldc, int bm, int bn, int tid)
{
    const int warp = tid >> 5, lane = tid & 31;
    const int wm = warp & 3, wn = warp >> 2;
    const int g = lane >> 2, t2 = (lane & 3) * 2;
    #pragma unroll
    for (int nt = 0; nt < 8; nt++) {
        int c0 = bn + wn * 64 + nt * 8 + t2;
        float2 bv = *(const float2*)(bias + c0);
        #pragma unroll
        for (int mt = 0; mt < 2; mt++) {
            int r0 = bm + wm * 32 + mt * 16 + g;
            *(__half2*)(C + (size_t)r0 * ldc + c0) =
                __floats2half2_rn(alpha * (acc[mt][nt][0] + bv.x),
                                  alpha * (acc[mt][nt][1] + bv.y));
            *(__half2*)(C + (size_t)(r0 + 8) * ldc + c0) =
                __floats2half2_rn(alpha * (acc[mt][nt][2] + bv.x),
                                  alpha * (acc[mt][nt][3] + bv.y));
        }
    }
}

// ---------------------------------------------------------------------------
// fused Q + K + V projections; Q segment gathers its A rows via to_sem
__global__ __launch_bounds__(256, 2) void qkv_gemm(
    const float* __restrict__ bq, const float* __restrict__ bk,
    const float* __restrict__ bv, float qscale,
    const void* __restrict__ to_sem)
{
    extern __shared__ char smem[];
    const uint32_t sb = smem_u32(smem);
    const int tid = threadIdx.x;
    const int is64 = g_is64;
    int id = blockIdx.x;

    const __half* W; const float* bias; __half* C;
    float alpha; int bm, bn, gmode;
    if (id < 512) {
        W = g_WQh; bias = bq; C = g_Qh; alpha = qscale; gmode = 1;
        bm = (id >> 3) * 128; bn = (id & 7) * 128;
    } else if (id < 1536) {
        int t = id - 512;
        W = g_WKh; bias = bk; C = g_Kh; alpha = 1.0f; gmode = 0;
        bm = (t >> 3) * 128; bn = (t & 7) * 128;
    } else {
        int t = id - 1536;
        W = g_WVh; bias = bv; C = g_Vh; alpha = 1.0f; gmode = 0;
        bm = (t >> 3) * 128; bn = (t & 7) * 128;
    }

    float acc[2][8][4];
    #pragma unroll
    for (int i = 0; i < 2; i++)
        #pragma unroll
        for (int j = 0; j < 8; j++)
            #pragma unroll
            for (int r = 0; r < 4; r++) acc[i][j][r] = 0.f;

    const __half* Ab = gmode ? g_ENCh : (g_ENCh + (size_t)bm * Dd);
    gemm_tile_core(acc, Ab, Dd, W + (size_t)bn * Dd, Dd, 16, sb, tid,
                   gmode, to_sem, bm, is64);
    epi_half(acc, bias, alpha, C, Dd, bm, bn, tid);
}

// Wc precompute: Wc[n,i] = sum_j Wp[n,j]*Wo[j,i]  (A=WPh ld KFn, W=WOTh ld Dd)
__global__ __launch_bounds__(256, 2) void wc_gemm() {
    extern __shared__ char smem[];
    const uint32_t sb = smem_u32(smem);
    const int tid = threadIdx.x;
    int id = blockIdx.x;
    int bm = (id >> 3) * 128, bn = (id & 7) * 128;

    float acc[2][8][4];
    #pragma unroll
    for (int i = 0; i < 2; i++)
        #pragma unroll
        for (int j = 0; j < 8; j++)
            #pragma unroll
            for (int r = 0; r < 4; r++) acc[i][j][r] = 0.f;

    gemm_tile_core(acc, g_WPh + (size_t)bm * KFn, KFn, g_WOTh + (size_t)bn * Dd, Dd,
                   16, sb, tid, 0, nullptr, 0, 0);
    epi_half(acc, g_zeros, 1.0f, g_Wch, Dd, bm, bn, tid);
}

// PE precompute: PE[t][n] = sum_k TEh[t][k] * WPh[n][1024+k]  (K=256)
__global__ __launch_bounds__(256, 2) void pe_gemm() {
    extern __shared__ char smem[];
    const uint32_t sb = smem_u32(smem);
    const int tid = threadIdx.x;
    int id = blockIdx.x;
    int bm = (id >> 3) * 128, bn = (id & 7) * 128;

    float acc[2][8][4];
    #pragma unroll
    for (int i = 0; i < 2; i++)
        #pragma unroll
        for (int j = 0; j < 8; j++)
            #pragma unroll
            for (int r = 0; r < 4; r++) acc[i][j][r] = 0.f;

    gemm_tile_core(acc, g_TEh + (size_t)bm * WDd, WDd,
                   g_WPh + (size_t)bn * KFn + Dd, KFn, 4, sb, tid, 0, nullptr, 0, 0);

    const int warp = tid >> 5, lane = tid & 31;
    const int wm = warp & 3, wn = warp >> 2;
    const int g = lane >> 2, t2 = (lane & 3) * 2;
    #pragma unroll
    for (int nt = 0; nt < 8; nt++) {
        int c0 = bn + wn * 64 + nt * 8 + t2;
        #pragma unroll
        for (int mt = 0; mt < 2; mt++) {
            int r0 = bm + wm * 32 + mt * 16 + g;
            float2 o0 = {acc[mt][nt][0], acc[mt][nt][1]};
            float2 o1 = {acc[mt][nt][2], acc[mt][nt][3]};
            *(float2*)(g_PE + (size_t)r0 * Dd + c0)       = o0;
            *(float2*)(g_PE + (size_t)(r0 + 8) * Dd + c0) = o1;
        }
    }
}

// combined projection: emb = CTXh @ Wch^T + bc + PE[tt]; dual store / EMB
__global__ __launch_bounds__(256, 2) void c_gemm(const void* __restrict__ tt,
                                                 float* __restrict__ out, int direct) {
    extern __shared__ char smem[];
    const uint32_t sb = smem_u32(smem);
    const int tid = threadIdx.x;
    int id = blockIdx.x;
    int bm = (id >> 3) * 128, bn = (id & 7) * 128;

    float acc[2][8][4];
    #pragma unroll
    for (int i = 0; i < 2; i++)
        #pragma unroll
        for (int j = 0; j < 8; j++)
            #pragma unroll
            for (int r = 0; r < 4; r++) acc[i][j][r] = 0.f;

    gemm_tile_core(acc, g_CTXh + (size_t)bm * Dd, Dd, g_Wch + (size_t)bn * Dd, Dd,
                   16, sb, tid, 0, nullptr, 0, 0);

    const int warp = tid >> 5, lane = tid & 31;
    const int wm = warp & 3, wn = warp >> 2;
    const int g = lane >> 2, t2 = (lane & 3) * 2;
    const int is64 = g_is64;

    int rows[2][2];
    const float* pe[2][2];
    #pragma unroll
    for (int mt = 0; mt < 2; mt++) {
        int r0 = bm + wm * 32 + mt * 16 + g;
        rows[mt][0] = r0;
        rows[mt][1] = r0 + 8;
        pe[mt][0] = g_PE + (size_t)load_idx_i(tt, r0,     is64) * Dd;
        pe[mt][1] = g_PE + (size_t)load_idx_i(tt, r0 + 8, is64) * Dd;
    }

    #pragma unroll
    for (int nt = 0; nt < 8; nt++) {
        int c0 = bn + wn * 64 + nt * 8 + t2;
        float2 bv = *(const float2*)(g_bc + c0);
        #pragma unroll
        for (int mt = 0; mt < 2; mt++) {
            float2 pa = *(const float2*)(pe[mt][0] + c0);
            float2 pb = *(const float2*)(pe[mt][1] + c0);
            int r0 = rows[mt][0], rb = rows[mt][1];
            float2 o0 = {acc[mt][nt][0] + bv.x + pa.x, acc[mt][nt][1] + bv.y + pa.y};
            float2 o1 = {acc[mt][nt][2] + bv.x + pb.x, acc[mt][nt][3] + bv.y + pb.y};
            if (direct) {
                int b0 = r0 >> 9, l0 = r0 & 511;
                int b1 = rb >> 9, l1 = rb & 511;
                *(float2*)(out + (size_t)r0 * Dd + c0) = o0;
                *(float2*)(out + (size_t)rb * Dd + c0) = o1;
                *(float2*)(out + T1c + ((size_t)b0 * (Ls+1) + l0 + 1) * Dd + c0) = o0;
                *(float2*)(out + T1c + ((size_t)b1 * (Ls+1) + l1 + 1) * Dd + c0) = o1;
            } else {
                *(float2*)(g_EMB + (size_t)r0 * Dd + c0) = o0;
                *(float2*)(g_EMB + (size_t)rb * Dd + c0) = o1;
            }
        }
    }
}

// ---------------------------------------------------------------------------
// fp32 -> fp16 conversions (7 segs) + dtype detect (seg 7)
__global__ void f2h_all(const float* __restrict__ e, const float* __restrict__ q,
                        const float* __restrict__ k, const float* __restrict__ v,
                        const float* __restrict__ o, const float* __restrict__ p,
                        const float* __restrict__ te,
                        const void* __restrict__ to_sem) {
    int seg = blockIdx.y;
    if (seg == 7) {
        __shared__ int nz;
        if (threadIdx.x == 0) nz = 0;
        __syncthreads();
        if (blockIdx.x == 0) {
            const int* qw = (const int*)to_sem;
            int bad = 0;
            for (int i = threadIdx.x * 2 + 1; i < 8192; i += 2 * blockDim.x)
                if (qw[i] != 0) bad = 1;
            if (bad) atomicAdd(&nz, 1);
            __syncthreads();
            if (threadIdx.x == 0) g_is64 = (nz == 0) ? 1 : 0;
        }
        return;
    }
    const float* srcs[7] = {e, q, k, v, o, p, te};
    __half* dsts[7] = {g_ENCh, g_WQh, g_WKh, g_WVh, g_WOh, g_WPh, g_TEh};
    const int n8s[7] = {BSn*Dd/8, Dd*Dd/8, Dd*Dd/8, Dd*Dd/8, Dd*Dd/8, Dd*KFn/8,
                        VOCP*WDd/8};
    const int vr8 = VOCR*WDd/8;
    const float* src = srcs[seg];
    __half* dst = dsts[seg];
    int n8 = n8s[seg];
    for (int i = blockIdx.x * blockDim.x + threadIdx.x; i < n8;
         i += gridDim.x * blockDim.x) {
        float4 a, b;
        if (seg == 6 && i >= vr8) {
            a = make_float4(0.f, 0.f, 0.f, 0.f);
            b = a;
        } else {
            a = ((const float4*)src)[2*i];
            b = ((const float4*)src)[2*i+1];
        }
        __half2 h[4];
        h[0] = __floats2half2_rn(a.x, a.y);
        h[1] = __floats2half2_rn(a.z, a.w);
        h[2] = __floats2half2_rn(b.x, b.y);
        h[3] = __floats2half2_rn(b.z, b.w);
        ((float4*)dst)[i] = *(float4*)h;
    }
}

// Wo transpose (fp32 source -> fp16 WOT), smem-tiled
__global__ void transpose_wo(const float* __restrict__ wo) {
    __shared__ float t[32][33];
    int bx = blockIdx.x * 32, by = blockIdx.y * 32;
    int x = threadIdx.x, y0 = threadIdx.y;
    #pragma unroll
    for (int dy = 0; dy < 32; dy += 8)
        t[y0 + dy][x] = wo[(size_t)(by + y0 + dy) * Dd + bx + x];
    __syncthreads();
    #pragma unroll
    for (int dy = 0; dy < 32; dy += 8) {
        int i = bx + y0 + dy;
        int j = by + x;
        g_WOTh[(size_t)i * Dd + j] = __float2half(t[x][y0 + dy]);
    }
}

// bc = Wp1·bo + b_proj (fp32 exact); one BLOCK per output, parallel reduction
__global__ __launch_bounds__(128) void bc_kernel(const float* __restrict__ wp,
                                                 const float* __restrict__ bo,
                                                 const float* __restrict__ bp) {
    __shared__ float wsum[4];
    int n = blockIdx.x;
    int tid = threadIdx.x;
    const float* row = wp + (size_t)n * KFn;
    float s = 0.f;
    // 128 threads x 8 elems = 1024, float2 strided
    for (int k = tid * 2; k < Dd; k += 256) {
        float2 a = *(const float2*)(row + k);
        float2 b = *(const float2*)(bo + k);
        s += a.x * b.x + a.y * b.y;
    }
    s += __shfl_xor_sync(0xffffffffu, s, 1);
    s += __shfl_xor_sync(0xffffffffu, s, 2);
    s += __shfl_xor_sync(0xffffffffu, s, 4);
    s += __shfl_xor_sync(0xffffffffu, s, 8);
    s += __shfl_xor_sync(0xffffffffu, s, 16);
    if ((tid & 31) == 0) wsum[tid >> 5] = s;
    __syncthreads();
    if (tid == 0)
        g_bc[n] = wsum[0] + wsum[1] + wsum[2] + wsum[3] + bp[n];
}

// ---------------------------------------------------------------------------
// bucket build (blocks 0..15) + root rows of d_out (blocks 16..31)
__global__ __launch_bounds__(1024) void build_buckets(const void* __restrict__ sem_syn,
                                                      const float* __restrict__ root,
                                                      float* __restrict__ out,
                                                      int direct) {
    if (blockIdx.x >= Bz) {
        if (direct) {
            int b = blockIdx.x - Bz;
            if (threadIdx.x < 256)
                ((float4*)(out + (size_t)T1c + (size_t)b * (Ls + 1) * Dd))[threadIdx.x] =
                    ((const float4*)root)[threadIdx.x];
        }
        return;
    }
    int b = blockIdx.x;
    int j = threadIdx.x;
    const int is64 = g_is64;
    if (j < Ls) g_bcnt[b * Ls + j] = 0;
    __syncthreads();
    long long v = is64 ? ((const long long*)sem_syn)[b * Ss + j]
                       : (long long)((const int*)sem_syn)[b * Ss + j];
    if (v >= 1 && v <= Ls) {
        int i = (int)v - 1;
        int slot = atomicAdd(&g_bcnt[b * Ls + i], 1);
        if (slot < BKT) g_bkt[(b * Ls + i) * BKT + slot] = (unsigned short)j;
    }
}

// ---------------------------------------------------------------------------
// Sparse masked attention using precomputed buckets; ~3KB smem.
__global__ __launch_bounds__(128) void attn_kernel(
    const void* __restrict__ to_sem, const void* __restrict__ sem_syn)
{
    int bl = blockIdx.x;
    int b = bl >> 9, i = bl & 511;
    int tid = threadIdx.x;

    __shared__ int   s_idx[BKT + 8];
    __shared__ float s_sc[Hh][BKT + 8];
    __shared__ int   s_total;

    const int is64 = g_is64;
    const int base = b * Ss;
    const long long target = (long long)(i + 1);

    int cnt = g_bcnt[bl];
    if (cnt > BKT) cnt = BKT;
    if (tid < cnt) s_idx[tid] = g_bkt[bl * BKT + tid];
    __syncthreads();

    if (tid == 0) {
        for (int x = 1; x < cnt; x++) {
            int key = s_idx[x];
            int y = x - 1;
            while (y >= 0 && s_idx[y] > key) { s_idx[y + 1] = s_idx[y]; y--; }
            s_idx[y + 1] = key;
        }
        int jself = load_idx_i(to_sem, bl, is64);
        long long vs = is64 ? ((const long long*)sem_syn)[base + jself]
                            : (long long)((const int*)sem_syn)[base + jself];
        int M = cnt;
        if (vs != target) { s_idx[M] = jself; M++; }
        s_total = M;
    }
    __syncthreads();
    const int M = s_total;

    int h = tid >> 4, l16 = tid & 15;
    float qr[8];
    {
        uint4 u = *(const uint4*)(g_Qh + (size_t)bl * Dd + h * DHd + l16 * 8);
        const __half2* hp = (const __half2*)&u;
        float2 f0 = __half22float2(hp[0]), f1 = __half22float2(hp[1]);
        float2 f2 = __half22float2(hp[2]), f3 = __half22float2(hp[3]);
        qr[0]=f0.x; qr[1]=f0.y; qr[2]=f1.x; qr[3]=f1.y;
        qr[4]=f2.x; qr[5]=f2.y; qr[6]=f3.x; qr[7]=f3.y;
    }

    for (int m = 0; m < M; m++) {
        int j = s_idx[m];
        uint4 u = *(const uint4*)(g_Kh + (size_t)(base + j) * Dd + h * DHd + l16 * 8);
        const __half2* hp = (const __half2*)&u;
        float2 k0 = __half22float2(hp[0]), k1 = __half22float2(hp[1]);
        float2 k2 = __half22float2(hp[2]), k3 = __half22float2(hp[3]);
        float p = qr[0]*k0.x + qr[1]*k0.y + qr[2]*k1.x + qr[3]*k1.y
                + qr[4]*k2.x + qr[5]*k2.y + qr[6]*k3.x + qr[7]*k3.y;
        p += __shfl_xor_sync(0xffffffffu, p, 1);
        p += __shfl_xor_sync(0xffffffffu, p, 2);
        p += __shfl_xor_sync(0xffffffffu, p, 4);
        p += __shfl_xor_sync(0xffffffffu, p, 8);
        if (l16 == 0) s_sc[h][m] = p;
    }
    __syncthreads();

    float mx = -3.0e38f;
    for (int m = 0; m < M; m++) mx = fmaxf(mx, s_sc[h][m]);
    float den = 0.f;
    for (int m = 0; m < M; m++) den += expf(s_sc[h][m] - mx);

    float acc[8];
    #pragma unroll
    for (int c = 0; c < 8; c++) acc[c] = 0.f;
    for (int m = 0; m < M; m++) {
        float p = expf(s_sc[h][m] - mx);
        int j = s_idx[m];
        uint4 u = *(const uint4*)(g_Vh + (size_t)(base + j) * Dd + h * DHd + l16 * 8);
        const __half2* hp = (const __half2*)&u;
        float2 v0 = __half22float2(hp[0]), v1 = __half22float2(hp[1]);
        float2 v2 = __half22float2(hp[2]), v3 = __half22float2(hp[3]);
        acc[0] += p * v0.x; acc[1] += p * v0.y; acc[2] += p * v1.x; acc[3] += p * v1.y;
        acc[4] += p * v2.x; acc[5] += p * v2.y; acc[6] += p * v3.x; acc[7] += p * v3.y;
    }
    float inv = 1.0f / den;
    __half2 h0 = __floats2half2_rn(acc[0]*inv, acc[1]*inv);
    __half2 h1 = __floats2half2_rn(acc[2]*inv, acc[3]*inv);
    __half2 h2 = __floats2half2_rn(acc[4]*inv, acc[5]*inv);
    __half2 h3 = __floats2half2_rn(acc[6]*inv, acc[7]*inv);
    uint4 u = { *(uint32_t*)&h0, *(uint32_t*)&h1, *(uint32_t*)&h2, *(uint32_t*)&h3 };
    *(uint4*)(g_CTXh + (size_t)bl * Dd + h * DHd + l16 * 8) = u;
}

// ---------------------------------------------------------------------------
// fallback output packer (only used when out_size doesn't match full tuple)
__global__ void write_out(const float* __restrict__ root, float* __restrict__ out,
                          int out_size) {
    const int T1 = T1c, T2 = T2c;
    int base2, n;
    if (out_size >= T1 + T2)      { base2 = T1; n = T1 + T2; }
    else if (out_size == T2)      { base2 = 0;  n = T2; }
    else                          { base2 = -1; n = T1; }
    int n4 = n >> 2;
    for (int i4 = blockIdx.x * blockDim.x + threadIdx.x; i4 < n4;
         i4 += gridDim.x * blockDim.x) {
        int e = i4 << 2;
        float4 val;
        if (base2 >= 0 && e >= base2) {
            int off = e - base2;
            int b = off / ((Ls + 1) * Dd);
            int r = off - b * ((Ls + 1) * Dd);
            int l = r >> 10;
            int dd = r & (Dd - 1);
            if (l == 0)
                val = ((const float4*)root)[dd >> 2];
            else
                val = ((const float4*)(g_EMB + ((size_t)(b * Ls + l - 1) << 10)))[dd >> 2];
        } else {
            val = ((const float4*)g_EMB)[i4];
        }
        ((float4*)out)[i4] = val;
    }
}

// ---------------------------------------------------------------------------
extern "C" void kernel_launch(void* const* d_in, const int* in_sizes, int n_in,
                              void* d_out, int out_size) {
    const float* enc     = (const float*)d_in[0];
    const void*  to_sem  = d_in[1];
    const void*  tt      = d_in[2];
    const void*  sem_syn = d_in[3];
    const float* bq = (const float*)d_in[5];
    const float* bk = (const float*)d_in[7];
    const float* bv = (const float*)d_in[9];
    const float* wo = (const float*)d_in[10];
    const float* bo = (const float*)d_in[11];
    const float* type_emb = (const float*)d_in[12];
    const float* w_proj   = (const float*)d_in[13];
    const float* b_proj   = (const float*)d_in[14];
    const float* root     = (const float*)d_in[15];

    cudaFuncSetAttribute(qkv_gemm, cudaFuncAttributeMaxDynamicSharedMemorySize, SM_TOT);
    cudaFuncSetAttribute(wc_gemm,  cudaFuncAttributeMaxDynamicSharedMemorySize, SM_TOT);
    cudaFuncSetAttribute(pe_gemm,  cudaFuncAttributeMaxDynamicSharedMemorySize, SM_TOT);
    cudaFuncSetAttribute(c_gemm,   cudaFuncAttributeMaxDynamicSharedMemorySize, SM_TOT);

    const float qscale = 0.08838834764831843f;   // 1/sqrt(128)
    const int direct = (out_size >= T1c + T2c);

    // conversions + dtype detect
    f2h_all<<<dim3(1024, 8), 256>>>(enc, (const float*)d_in[4], (const float*)d_in[6],
                                    (const float*)d_in[8], wo,
                                    w_proj, type_emb, to_sem);
    // precomputes (off the qkv critical path)
    transpose_wo<<<dim3(32, 32), dim3(32, 8)>>>(wo);
    bc_kernel<<<Dd, 128>>>(w_proj, bo, b_proj);
    wc_gemm<<<64, 256, SM_TOT>>>();
    pe_gemm<<<64, 256, SM_TOT>>>();
    build_buckets<<<2 * Bz, 1024>>>(sem_syn, root, (float*)d_out, direct);

    qkv_gemm<<<2560, 256, SM_TOT>>>(bq, bk, bv, qscale, to_sem);

    attn_kernel<<<BLn, 128>>>(to_sem, sem_syn);

    // single combined projection replaces o_gemm + p_gemm
    c_gemm<<<512, 256, SM_TOT>>>(tt, (float*)d_out, direct);

    if (!direct) write_out<<<2048, 256>>>(root, (float*)d_out, out_size);
}

// round 16
// speedup vs baseline: 1.2514x; 1.0608x over previous
#include <cuda_runtime.h>
#include <cuda_fp16.h>
#include <cstdint>

// Problem constants
#define Bz   16
#define Ss   1024
#define Ls   512
#define Dd   1024
#define Hh   8
#define DHd  128
#define WDd  256
#define VOCP 1024
#define VOCR 1000
#define BLn  (Bz*Ls)      // 8192
#define BSn  (Bz*Ss)      // 16384
#define KFn  (Dd+WDd)     // 1280
#define T1c  (BLn*Dd)
#define T2c  (Bz*(Ls+1)*Dd)
#define BKT  64

// Scratch (static device globals — allocation-free per harness rules)
__device__ __align__(128) __half g_ENCh[BSn*Dd];
__device__ __align__(128) __half g_WQh [Dd*Dd];
__device__ __align__(128) __half g_WKh [Dd*Dd];
__device__ __align__(128) __half g_WVh [Dd*Dd];
__device__ __align__(128) __half g_WOTh[Dd*Dd];       // Wo^T fp16
__device__ __align__(128) __half g_WPh [Dd*KFn];
__device__ __align__(128) __half g_Wch [Dd*Dd];       // Wp[:, :1024] @ Wo  (fp16)
__device__ __align__(128) __half g_TEh [VOCP*WDd];
__device__ __align__(128) float  g_PE  [VOCP*Dd];     // type_emb @ Wp[:,1024:]^T
__device__ __align__(128) float  g_bc  [Dd];          // Wp1·bo + b_proj (fp32)
__device__ __align__(128) float  g_zeros[Dd];         // zero-initialized
__device__ __align__(128) __half g_Qh  [BLn*Dd];
__device__ __align__(128) __half g_Kh  [BSn*Dd];
__device__ __align__(128) __half g_Vh  [BSn*Dd];
__device__ __align__(128) __half g_CTXh[BLn*Dd];
__device__ __align__(128) float  g_EMB [BLn*Dd];
__device__ int            g_bcnt[BLn];
__device__ unsigned short g_bkt [BLn*BKT];
__device__ int g_is64;

// ---------------------------------------------------------------------------
__device__ __forceinline__ uint32_t smem_u32(const void* p) {
    uint32_t a;
    asm("{ .reg .u64 t; cvta.to.shared.u64 t, %1; cvt.u32.u64 %0, t; }" : "=r"(a) : "l"(p));
    return a;
}

__device__ __forceinline__ void cp16(uint32_t dst, const void* src) {
    asm volatile("cp.async.cg.shared.global [%0], [%1], 16;" :: "r"(dst), "l"(src));
}
#define CP_COMMIT() asm volatile("cp.async.commit_group;" ::: "memory")
#define CP_WAIT(n)  asm volatile("cp.async.wait_group %0;" :: "n"(n) : "memory")

#define LDSM4(r, addr) \
    asm volatile("ldmatrix.sync.aligned.m8n8.x4.shared.b16 {%0,%1,%2,%3}, [%4];" \
        : "=r"((r)[0]), "=r"((r)[1]), "=r"((r)[2]), "=r"((r)[3]) : "r"(addr))

#define MMA16816(c, a, b0, b1) \
    asm volatile("mma.sync.aligned.m16n8k16.row.col.f32.f16.f16.f32 " \
        "{%0,%1,%2,%3}, {%4,%5,%6,%7}, {%8,%9}, {%0,%1,%2,%3};" \
        : "+f"((c)[0]), "+f"((c)[1]), "+f"((c)[2]), "+f"((c)[3]) \
        : "r"((a)[0]), "r"((a)[1]), "r"((a)[2]), "r"((a)[3]), "r"(b0), "r"(b1))

#define STG_B 32768
#define SM_TOT (3*STG_B)

__device__ __forceinline__ int load_idx_i(const void* p, int i, int is64) {
    return is64 ? (int)((const long long*)p)[i] : ((const int*)p)[i];
}

// ---------------------------------------------------------------------------
// GEMM core (NT): acc += A[bm:bm+128, :K] * W[bn:bn+128, :K]^T
__device__ __forceinline__ void gemm_tile_core(
    float acc[2][8][4],
    const __half* __restrict__ Ab, int lda,
    const __half* __restrict__ Wb, int ldw,
    int KT, uint32_t sb, int tid,
    int gmode, const void* __restrict__ ts, int gbm, int is64)
{
    const int warp = tid >> 5, lane = tid & 31;
    const int wm = warp & 3, wn = warp >> 2;

    const __half* aptr[4];
    const __half* wptr[4];
    uint32_t soff[4];
    #pragma unroll
    for (int i = 0; i < 4; i++) {
        int c = tid + i * 256;
        int row = c >> 3, ch = c & 7;
        soff[i] = (uint32_t)((row << 7) + ((ch << 4) ^ ((row & 7) << 4)));
        if (gmode) {
            int m = gbm + row;
            int idx = load_idx_i(ts, m, is64);
            aptr[i] = Ab + (((size_t)(m >> 9) << 10) + (size_t)idx) * Dd + ch * 8;
        } else {
            aptr[i] = Ab + (size_t)row * lda + ch * 8;
        }
        wptr[i] = Wb + (size_t)row * ldw + ch * 8;
    }

    auto load = [&](int stage, int kt) {
        const int k0 = kt * 64;
        uint32_t sa = sb + stage * STG_B;
        uint32_t sw = sa + 16384;
        #pragma unroll
        for (int i = 0; i < 4; i++) {
            cp16(sa + soff[i], aptr[i] + k0);
            cp16(sw + soff[i], wptr[i] + k0);
        }
        CP_COMMIT();
    };

    load(0, 0);
    load(1, 1);

    const int rlA = (lane & 7) + ((lane >> 3) & 1) * 8;
    const int caA = ((lane >> 4) & 1) << 4;
    const int rlB = (lane & 7) + ((lane >> 4) & 1) * 8;
    const int caB = ((lane >> 3) & 1) << 4;
    const uint32_t swA = (uint32_t)(rlA & 7) << 4;
    const uint32_t swB = (uint32_t)(rlB & 7) << 4;
    const uint32_t rowA0 = (uint32_t)((wm * 32 +  0 + rlA) << 7);
    const uint32_t rowA1 = (uint32_t)((wm * 32 + 16 + rlA) << 7);
    const uint32_t rowB0 = (uint32_t)((wn * 64 +  0 + rlB) << 7);
    const uint32_t rowB1 = (uint32_t)((wn * 64 + 16 + rlB) << 7);
    const uint32_t rowB2 = (uint32_t)((wn * 64 + 32 + rlB) << 7);
    const uint32_t rowB3 = (uint32_t)((wn * 64 + 48 + rlB) << 7);

    for (int kt = 0; kt < KT; kt++) {
        if (kt + 2 < KT) { CP_WAIT(1); } else { CP_WAIT(0); }
        __syncthreads();
        if (kt + 2 < KT) load((kt + 2) % 3, kt + 2);

        uint32_t ab = sb + (kt % 3) * STG_B;
        uint32_t bb = ab + 16384;

        #pragma unroll
        for (int q = 0; q < 4; q++) {
            const uint32_t cA = (uint32_t)((q << 5) + caA) ^ swA;
            const uint32_t cB = (uint32_t)((q << 5) + caB) ^ swB;
            uint32_t a[2][4], b[4][4];
            LDSM4(a[0], ab + rowA0 + cA);
            LDSM4(a[1], ab + rowA1 + cA);
            LDSM4(b[0], bb + rowB0 + cB);
            LDSM4(b[1], bb + rowB1 + cB);
            LDSM4(b[2], bb + rowB2 + cB);
            LDSM4(b[3], bb + rowB3 + cB);
            #pragma unroll
            for (int mt = 0; mt < 2; mt++)
                #pragma unroll
                for (int np = 0; np < 4; np++) {
                    MMA16816(acc[mt][2*np],     a[mt], b[np][0], b[np][1]);
                    MMA16816(acc[mt][2*np + 1], a[mt], b[np][2], b[np][3]);
                }
        }
    }
}

// fp16 epilogue
__device__ __forceinline__ void epi_half(
    float acc[2][8][4], const float* __restrict__ bias, float alpha,
    __half* __restrict__ C, int ldc, int bm, int bn, int tid)
{
    const int warp = tid >> 5, lane = tid & 31;
    const int wm = warp & 3, wn = warp >> 2;
    const int g = lane >> 2, t2 = (lane & 3) * 2;
    #pragma unroll
    for (int nt = 0; nt < 8; nt++) {
        int c0 = bn + wn * 64 + nt * 8 + t2;
        float2 bv = *(const float2*)(bias + c0);
        #pragma unroll
        for (int mt = 0; mt < 2; mt++) {
            int r0 = bm + wm * 32 + mt * 16 + g;
            *(__half2*)(C + (size_t)r0 * ldc + c0) =
                __floats2half2_rn(alpha * (acc[mt][nt][0] + bv.x),
                                  alpha * (acc[mt][nt][1] + bv.y));
            *(__half2*)(C + (size_t)(r0 + 8) * ldc + c0) =
                __floats2half2_rn(alpha * (acc[mt][nt][2] + bv.x),
                                  alpha * (acc[mt][nt][3] + bv.y));
        }
    }
}

// ---------------------------------------------------------------------------
// mega GEMM launch: [0,64) Wc, [64,128) PE, [128,640) Q(gather),
// [640,1664) K, [1664,2688) V
__global__ __launch_bounds__(256, 2) void qkv_gemm(
    const float* __restrict__ bq, const float* __restrict__ bk,
    const float* __restrict__ bv, float qscale,
    const void* __restrict__ to_sem)
{
    extern __shared__ char smem[];
    const uint32_t sb = smem_u32(smem);
    const int tid = threadIdx.x;
    const int is64 = g_is64;
    int id = blockIdx.x;

    const __half* A; int lda;
    const __half* W; int ldw;
    const float* bias; __half* C;
    float alpha; int bm, bn, gmode, KT, seg;
    if (id < 64) {            // Wc = Wp1 @ Wo
        seg = 0; KT = 16; gmode = 0;
        bm = (id >> 3) * 128; bn = (id & 7) * 128;
        A = g_WPh + (size_t)bm * KFn; lda = KFn;
        W = g_WOTh + (size_t)bn * Dd; ldw = Dd;
        bias = g_zeros; C = g_Wch; alpha = 1.0f;
    } else if (id < 128) {    // PE = TE @ Wp2^T
        int t = id - 64;
        seg = 1; KT = 4; gmode = 0;
        bm = (t >> 3) * 128; bn = (t & 7) * 128;
        A = g_TEh + (size_t)bm * WDd; lda = WDd;
        W = g_WPh + (size_t)bn * KFn + Dd; ldw = KFn;
        bias = g_zeros; C = nullptr; alpha = 1.0f;
    } else if (id < 640) {    // Q (gathered A)
        int t = id - 128;
        seg = 2; KT = 16; gmode = 1;
        bm = (t >> 3) * 128; bn = (t & 7) * 128;
        A = g_ENCh; lda = Dd;
        W = g_WQh + (size_t)bn * Dd; ldw = Dd;
        bias = bq; C = g_Qh; alpha = qscale;
    } else if (id < 1664) {   // K
        int t = id - 640;
        seg = 2; KT = 16; gmode = 0;
        bm = (t >> 3) * 128; bn = (t & 7) * 128;
        A = g_ENCh + (size_t)bm * Dd; lda = Dd;
        W = g_WKh + (size_t)bn * Dd; ldw = Dd;
        bias = bk; C = g_Kh; alpha = 1.0f;
    } else {                  // V
        int t = id - 1664;
        seg = 2; KT = 16; gmode = 0;
        bm = (t >> 3) * 128; bn = (t & 7) * 128;
        A = g_ENCh + (size_t)bm * Dd; lda = Dd;
        W = g_WVh + (size_t)bn * Dd; ldw = Dd;
        bias = bv; C = g_Vh; alpha = 1.0f;
    }

    float acc[2][8][4];
    #pragma unroll
    for (int i = 0; i < 2; i++)
        #pragma unroll
        for (int j = 0; j < 8; j++)
            #pragma unroll
            for (int r = 0; r < 4; r++) acc[i][j][r] = 0.f;

    gemm_tile_core(acc, A, lda, W, ldw, KT, sb, tid, gmode, to_sem, bm, is64);

    if (seg == 1) {
        // fp32 store to g_PE
        const int warp = tid >> 5, lane = tid & 31;
        const int wm = warp & 3, wn = warp >> 2;
        const int g = lane >> 2, t2 = (lane & 3) * 2;
        #pragma unroll
        for (int nt = 0; nt < 8; nt++) {
            int c0 = bn + wn * 64 + nt * 8 + t2;
            #pragma unroll
            for (int mt = 0; mt < 2; mt++) {
                int r0 = bm + wm * 32 + mt * 16 + g;
                float2 o0 = {acc[mt][nt][0], acc[mt][nt][1]};
                float2 o1 = {acc[mt][nt][2], acc[mt][nt][3]};
                *(float2*)(g_PE + (size_t)r0 * Dd + c0)       = o0;
                *(float2*)(g_PE + (size_t)(r0 + 8) * Dd + c0) = o1;
            }
        }
    } else {
        epi_half(acc, bias, alpha, C, Dd, bm, bn, tid);
    }
}

// combined projection: emb = CTXh @ Wch^T + bc + PE[tt]; dual store / EMB
__global__ __launch_bounds__(256, 2) void c_gemm(const void* __restrict__ tt,
                                                 float* __restrict__ out, int direct) {
    extern __shared__ char smem[];
    const uint32_t sb = smem_u32(smem);
    const int tid = threadIdx.x;
    int id = blockIdx.x;
    int bm = (id >> 3) * 128, bn = (id & 7) * 128;

    float acc[2][8][4];
    #pragma unroll
    for (int i = 0; i < 2; i++)
        #pragma unroll
        for (int j = 0; j < 8; j++)
            #pragma unroll
            for (int r = 0; r < 4; r++) acc[i][j][r] = 0.f;

    gemm_tile_core(acc, g_CTXh + (size_t)bm * Dd, Dd, g_Wch + (size_t)bn * Dd, Dd,
                   16, sb, tid, 0, nullptr, 0, 0);

    const int warp = tid >> 5, lane = tid & 31;
    const int wm = warp & 3, wn = warp >> 2;
    const int g = lane >> 2, t2 = (lane & 3) * 2;
    const int is64 = g_is64;

    int rows[2][2];
    const float* pe[2][2];
    #pragma unroll
    for (int mt = 0; mt < 2; mt++) {
        int r0 = bm + wm * 32 + mt * 16 + g;
        rows[mt][0] = r0;
        rows[mt][1] = r0 + 8;
        pe[mt][0] = g_PE + (size_t)load_idx_i(tt, r0,     is64) * Dd;
        pe[mt][1] = g_PE + (size_t)load_idx_i(tt, r0 + 8, is64) * Dd;
    }

    #pragma unroll
    for (int nt = 0; nt < 8; nt++) {
        int c0 = bn + wn * 64 + nt * 8 + t2;
        float2 bv = *(const float2*)(g_bc + c0);
        #pragma unroll
        for (int mt = 0; mt < 2; mt++) {
            float2 pa = *(const float2*)(pe[mt][0] + c0);
            float2 pb = *(const float2*)(pe[mt][1] + c0);
            int r0 = rows[mt][0], rb = rows[mt][1];
            float2 o0 = {acc[mt][nt][0] + bv.x + pa.x, acc[mt][nt][1] + bv.y + pa.y};
            float2 o1 = {acc[mt][nt][2] + bv.x + pb.x, acc[mt][nt][3] + bv.y + pb.y};
            if (direct) {
                int b0 = r0 >> 9, l0 = r0 & 511;
                int b1 = rb >> 9, l1 = rb & 511;
                *(float2*)(out + (size_t)r0 * Dd + c0) = o0;
                *(float2*)(out + (size_t)rb * Dd + c0) = o1;
                *(float2*)(out + T1c + ((size_t)b0 * (Ls+1) + l0 + 1) * Dd + c0) = o0;
                *(float2*)(out + T1c + ((size_t)b1 * (Ls+1) + l1 + 1) * Dd + c0) = o1;
            } else {
                *(float2*)(g_EMB + (size_t)r0 * Dd + c0) = o0;
                *(float2*)(g_EMB + (size_t)rb * Dd + c0) = o1;
            }
        }
    }
}

// ---------------------------------------------------------------------------
// fp32 -> fp16 conversions (7 segs) + dtype detect (seg 7)
__global__ void f2h_all(const float* __restrict__ e, const float* __restrict__ q,
                        const float* __restrict__ k, const float* __restrict__ v,
                        const float* __restrict__ o, const float* __restrict__ p,
                        const float* __restrict__ te,
                        const void* __restrict__ to_sem) {
    int seg = blockIdx.y;
    if (seg == 7) {
        __shared__ int nz;
        if (threadIdx.x == 0) nz = 0;
        __syncthreads();
        if (blockIdx.x == 0) {
            const int* qw = (const int*)to_sem;
            int bad = 0;
            for (int i = threadIdx.x * 2 + 1; i < 8192; i += 2 * blockDim.x)
                if (qw[i] != 0) bad = 1;
            if (bad) atomicAdd(&nz, 1);
            __syncthreads();
            if (threadIdx.x == 0) g_is64 = (nz == 0) ? 1 : 0;
        }
        return;
    }
    // seg 4 converts Wo DIRECTLY TRANSPOSED? No — transpose handled in prep.
    const float* srcs[7] = {e, q, k, v, o, p, te};
    __half* dsts[7] = {g_ENCh, g_WQh, g_WKh, g_WVh, nullptr, g_WPh, g_TEh};
    const int n8s[7] = {BSn*Dd/8, Dd*Dd/8, Dd*Dd/8, Dd*Dd/8, 0, Dd*KFn/8,
                        VOCP*WDd/8};
    const int vr8 = VOCR*WDd/8;
    if (seg == 4) return;   // Wo handled by prep transpose
    const float* src = srcs[seg];
    __half* dst = dsts[seg];
    int n8 = n8s[seg];
    for (int i = blockIdx.x * blockDim.x + threadIdx.x; i < n8;
         i += gridDim.x * blockDim.x) {
        float4 a, b;
        if (seg == 6 && i >= vr8) {
            a = make_float4(0.f, 0.f, 0.f, 0.f);
            b = a;
        } else {
            a = ((const float4*)src)[2*i];
            b = ((const float4*)src)[2*i+1];
        }
        __half2 h[4];
        h[0] = __floats2half2_rn(a.x, a.y);
        h[1] = __floats2half2_rn(a.z, a.w);
        h[2] = __floats2half2_rn(b.x, b.y);
        h[3] = __floats2half2_rn(b.z, b.w);
        ((float4*)dst)[i] = *(float4*)h;
    }
}

// ---------------------------------------------------------------------------
// prep kernel (256 threads): [0,1024) Wo transpose tiles; [1024,2048) bc;
// [2048,2064) buckets; [2064,2080) root rows
__global__ __launch_bounds__(256) void prep(
    const float* __restrict__ wo, const float* __restrict__ wp,
    const float* __restrict__ bo, const float* __restrict__ bp,
    const void* __restrict__ sem_syn,
    const float* __restrict__ root, float* __restrict__ out, int direct)
{
    int id = blockIdx.x;
    int tid = threadIdx.x;

    if (id < 1024) {
        // Wo^T fp16: 32x32 tile; threads (x=tid&31, y0=tid>>5 in steps of 8)
        __shared__ float t[32][33];
        int bx = (id & 31) * 32, by = (id >> 5) * 32;
        int x = tid & 31, y0 = tid >> 5;
        #pragma unroll
        for (int dy = 0; dy < 32; dy += 8)
            t[y0 + dy][x] = wo[(size_t)(by + y0 + dy) * Dd + bx + x];
        __syncthreads();
        #pragma unroll
        for (int dy = 0; dy < 32; dy += 8) {
            int i = bx + y0 + dy;
            int j = by + x;
            g_WOTh[(size_t)i * Dd + j] = __float2half(t[x][y0 + dy]);
        }
        return;
    }
    if (id < 2048) {
        // bc[n] = Wp1[n,:]·bo + bp[n], 256-thread reduction
        __shared__ float wsum[8];
        int n = id - 1024;
        const float* row = wp + (size_t)n * KFn;
        float s = 0.f;
        for (int k = tid * 2; k < Dd; k += 512) {
            float2 a = *(const float2*)(row + k);
            float2 b = *(const float2*)(bo + k);
            s += a.x * b.x + a.y * b.y;
        }
        s += __shfl_xor_sync(0xffffffffu, s, 1);
        s += __shfl_xor_sync(0xffffffffu, s, 2);
        s += __shfl_xor_sync(0xffffffffu, s, 4);
        s += __shfl_xor_sync(0xffffffffu, s, 8);
        s += __shfl_xor_sync(0xffffffffu, s, 16);
        if ((tid & 31) == 0) wsum[tid >> 5] = s;
        __syncthreads();
        if (tid == 0) {
            float tot = bp[n];
            #pragma unroll
            for (int w = 0; w < 8; w++) tot += wsum[w];
            g_bc[n] = tot;
        }
        return;
    }
    if (id < 2048 + Bz) {
        // bucket build for batch b
        int b = id - 2048;
        const int is64 = g_is64;
        for (int j = tid; j < Ls; j += 256) g_bcnt[b * Ls + j] = 0;
        __syncthreads();
        for (int it = 0; it < 4; it++) {
            int j = it * 256 + tid;
            long long v = is64 ? ((const long long*)sem_syn)[b * Ss + j]
                               : (long long)((const int*)sem_syn)[b * Ss + j];
            if (v >= 1 && v <= Ls) {
                int i = (int)v - 1;
                int slot = atomicAdd(&g_bcnt[b * Ls + i], 1);
                if (slot < BKT) g_bkt[(b * Ls + i) * BKT + slot] = (unsigned short)j;
            }
        }
        return;
    }
    // root rows
    if (direct) {
        int b = id - 2048 - Bz;
        ((float4*)(out + (size_t)T1c + (size_t)b * (Ls + 1) * Dd))[tid] =
            ((const float4*)root)[tid];
    }
}

// ---------------------------------------------------------------------------
// Sparse masked attention using precomputed buckets; ~3KB smem.
__global__ __launch_bounds__(128) void attn_kernel(
    const void* __restrict__ to_sem, const void* __restrict__ sem_syn)
{
    int bl = blockIdx.x;
    int b = bl >> 9, i = bl & 511;
    int tid = threadIdx.x;

    __shared__ int   s_idx[BKT + 8];
    __shared__ float s_sc[Hh][BKT + 8];
    __shared__ int   s_total;

    const int is64 = g_is64;
    const int base = b * Ss;
    const long long target = (long long)(i + 1);

    int cnt = g_bcnt[bl];
    if (cnt > BKT) cnt = BKT;
    if (tid < cnt) s_idx[tid] = g_bkt[bl * BKT + tid];
    __syncthreads();

    if (tid == 0) {
        for (int x = 1; x < cnt; x++) {
            int key = s_idx[x];
            int y = x - 1;
            while (y >= 0 && s_idx[y] > key) { s_idx[y + 1] = s_idx[y]; y--; }
            s_idx[y + 1] = key;
        }
        int jself = load_idx_i(to_sem, bl, is64);
        long long vs = is64 ? ((const long long*)sem_syn)[base + jself]
                            : (long long)((const int*)sem_syn)[base + jself];
        int M = cnt;
        if (vs != target) { s_idx[M] = jself; M++; }
        s_total = M;
    }
    __syncthreads();
    const int M = s_total;

    int h = tid >> 4, l16 = tid & 15;
    float qr[8];
    {
        uint4 u = *(const uint4*)(g_Qh + (size_t)bl * Dd + h * DHd + l16 * 8);
        const __half2* hp = (const __half2*)&u;
        float2 f0 = __half22float2(hp[0]), f1 = __half22float2(hp[1]);
        float2 f2 = __half22float2(hp[2]), f3 = __half22float2(hp[3]);
        qr[0]=f0.x; qr[1]=f0.y; qr[2]=f1.x; qr[3]=f1.y;
        qr[4]=f2.x; qr[5]=f2.y; qr[6]=f3.x; qr[7]=f3.y;
    }

    for (int m = 0; m < M; m++) {
        int j = s_idx[m];
        uint4 u = *(const uint4*)(g_Kh + (size_t)(base + j) * Dd + h * DHd + l16 * 8);
        const __half2* hp = (const __half2*)&u;
        float2 k0 = __half22float2(hp[0]), k1 = __half22float2(hp[1]);
        float2 k2 = __half22float2(hp[2]), k3 = __half22float2(hp[3]);
        float p = qr[0]*k0.x + qr[1]*k0.y + qr[2]*k1.x + qr[3]*k1.y
                + qr[4]*k2.x + qr[5]*k2.y + qr[6]*k3.x + qr[7]*k3.y;
        p += __shfl_xor_sync(0xffffffffu, p, 1);
        p += __shfl_xor_sync(0xffffffffu, p, 2);
        p += __shfl_xor_sync(0xffffffffu, p, 4);
        p += __shfl_xor_sync(0xffffffffu, p, 8);
        if (l16 == 0) s_sc[h][m] = p;
    }
    __syncthreads();

    float mx = -3.0e38f;
    for (int m = 0; m < M; m++) mx = fmaxf(mx, s_sc[h][m]);
    float den = 0.f;
    for (int m = 0; m < M; m++) den += expf(s_sc[h][m] - mx);

    float acc[8];
    #pragma unroll
    for (int c = 0; c < 8; c++) acc[c] = 0.f;
    for (int m = 0; m < M; m++) {
        float p = expf(s_sc[h][m] - mx);
        int j = s_idx[m];
        uint4 u = *(const uint4*)(g_Vh + (size_t)(base + j) * Dd + h * DHd + l16 * 8);
        const __half2* hp = (const __half2*)&u;
        float2 v0 = __half22float2(hp[0]), v1 = __half22float2(hp[1]);
        float2 v2 = __half22float2(hp[2]), v3 = __half22float2(hp[3]);
        acc[0] += p * v0.x; acc[1] += p * v0.y; acc[2] += p * v1.x; acc[3] += p * v1.y;
        acc[4] += p * v2.x; acc[5] += p * v2.y; acc[6] += p * v3.x; acc[7] += p * v3.y;
    }
    float inv = 1.0f / den;
    __half2 h0 = __floats2half2_rn(acc[0]*inv, acc[1]*inv);
    __half2 h1 = __floats2half2_rn(acc[2]*inv, acc[3]*inv);
    __half2 h2 = __floats2half2_rn(acc[4]*inv, acc[5]*inv);
    __half2 h3 = __floats2half2_rn(acc[6]*inv, acc[7]*inv);
    uint4 u = { *(uint32_t*)&h0, *(uint32_t*)&h1, *(uint32_t*)&h2, *(uint32_t*)&h3 };
    *(uint4*)(g_CTXh + (size_t)bl * Dd + h * DHd + l16 * 8) = u;
}

// ---------------------------------------------------------------------------
// fallback output packer (only used when out_size doesn't match full tuple)
__global__ void write_out(const float* __restrict__ root, float* __restrict__ out,
                          int out_size) {
    const int T1 = T1c, T2 = T2c;
    int base2, n;
    if (out_size >= T1 + T2)      { base2 = T1; n = T1 + T2; }
    else if (out_size == T2)      { base2 = 0;  n = T2; }
    else                          { base2 = -1; n = T1; }
    int n4 = n >> 2;
    for (int i4 = blockIdx.x * blockDim.x + threadIdx.x; i4 < n4;
         i4 += gridDim.x * blockDim.x) {
        int e = i4 << 2;
        float4 val;
        if (base2 >= 0 && e >= base2) {
            int off = e - base2;
            int b = off / ((Ls + 1) * Dd);
            int r = off - b * ((Ls + 1) * Dd);
            int l = r >> 10;
            int dd = r & (Dd - 1);
            if (l == 0)
                val = ((const float4*)root)[dd >> 2];
            else
                val = ((const float4*)(g_EMB + ((size_t)(b * Ls + l - 1) << 10)))[dd >> 2];
        } else {
            val = ((const float4*)g_EMB)[i4];
        }
        ((float4*)out)[i4] = val;
    }
}

// ---------------------------------------------------------------------------
extern "C" void kernel_launch(void* const* d_in, const int* in_sizes, int n_in,
                              void* d_out, int out_size) {
    const float* enc     = (const float*)d_in[0];
    const void*  to_sem  = d_in[1];
    const void*  tt      = d_in[2];
    const void*  sem_syn = d_in[3];
    const float* bq = (const float*)d_in[5];
    const float* bk = (const float*)d_in[7];
    const float* bv = (const float*)d_in[9];
    const float* wo = (const float*)d_in[10];
    const float* bo = (const float*)d_in[11];
    const float* type_emb = (const float*)d_in[12];
    const float* w_proj   = (const float*)d_in[13];
    const float* b_proj   = (const float*)d_in[14];
    const float* root     = (const float*)d_in[15];

    cudaFuncSetAttribute(qkv_gemm, cudaFuncAttributeMaxDynamicSharedMemorySize, SM_TOT);
    cudaFuncSetAttribute(c_gemm,   cudaFuncAttributeMaxDynamicSharedMemorySize, SM_TOT);

    const float qscale = 0.08838834764831843f;   // 1/sqrt(128)
    const int direct = (out_size >= T1c + T2c);

    // conversions + dtype detect (Wo conversion folded into prep's transpose)
    f2h_all<<<dim3(1024, 8), 256>>>(enc, (const float*)d_in[4], (const float*)d_in[6],
                                    (const float*)d_in[8], wo,
                                    w_proj, type_emb, to_sem);
    // transpose + bc + buckets + root in ONE launch
    prep<<<2048 + 2 * Bz, 256>>>(wo, w_proj, bo, b_proj, sem_syn,
                                 root, (float*)d_out, direct);

    // Wc + PE + Q + K + V in ONE launch
    qkv_gemm<<<2688, 256, SM_TOT>>>(bq, bk, bv, qscale, to_sem);

    attn_kernel<<<BLn, 128>>>(to_sem, sem_syn);

    c_gemm<<<512, 256, SM_TOT>>>(tt, (float*)d_out, direct);

    if (!direct) write_out<<<2048, 256>>>(root, (float*)d_out, out_size);
}

// round 17
// speedup vs baseline: 1.2642x; 1.0103x over previous
#include <cuda_runtime.h>
#include <cuda_fp16.h>
#include <cstdint>

// Problem constants
#define Bz   16
#define Ss   1024
#define Ls   512
#define Dd   1024
#define Hh   8
#define DHd  128
#define WDd  256
#define VOCP 1024
#define VOCR 1000
#define BLn  (Bz*Ls)      // 8192
#define BSn  (Bz*Ss)      // 16384
#define KFn  (Dd+WDd)     // 1280
#define T1c  (BLn*Dd)
#define T2c  (Bz*(Ls+1)*Dd)
#define BKT  64

// Scratch (static device globals — allocation-free per harness rules)
__device__ __align__(128) __half g_ENCh[BSn*Dd];
__device__ __align__(128) __half g_WQh [Dd*Dd];
__device__ __align__(128) __half g_WKh [Dd*Dd];
__device__ __align__(128) __half g_WVh [Dd*Dd];
__device__ __align__(128) __half g_WOTh[Dd*Dd];       // Wo^T fp16
__device__ __align__(128) __half g_WPh [Dd*KFn];
__device__ __align__(128) __half g_Wch [Dd*Dd];       // Wp[:, :1024] @ Wo  (fp16)
__device__ __align__(128) __half g_TEh [VOCP*WDd];
__device__ __align__(128) float  g_PE  [VOCP*Dd];     // type_emb @ Wp[:,1024:]^T
__device__ __align__(128) float  g_bc  [Dd];          // Wp1·bo + b_proj (fp32)
__device__ __align__(128) float  g_zeros[Dd];         // zero-initialized
__device__ __align__(128) __half g_Qh  [BLn*Dd];
__device__ __align__(128) __half g_Kh  [BSn*Dd];
__device__ __align__(128) __half g_Vh  [BSn*Dd];
__device__ __align__(128) __half g_CTXh[BLn*Dd];
__device__ __align__(128) float  g_EMB [BLn*Dd];
__device__ int            g_bcnt[BLn];
__device__ unsigned short g_bkt [BLn*BKT];
__device__ int g_is64;

// ---------------------------------------------------------------------------
__device__ __forceinline__ uint32_t smem_u32(const void* p) {
    uint32_t a;
    asm("{ .reg .u64 t; cvta.to.shared.u64 t, %1; cvt.u32.u64 %0, t; }" : "=r"(a) : "l"(p));
    return a;
}

__device__ __forceinline__ void cp16(uint32_t dst, const void* src) {
    asm volatile("cp.async.cg.shared.global [%0], [%1], 16;" :: "r"(dst), "l"(src));
}
#define CP_COMMIT() asm volatile("cp.async.commit_group;" ::: "memory")
#define CP_WAIT(n)  asm volatile("cp.async.wait_group %0;" :: "n"(n) : "memory")

#define LDSM4(r, addr) \
    asm volatile("ldmatrix.sync.aligned.m8n8.x4.shared.b16 {%0,%1,%2,%3}, [%4];" \
        : "=r"((r)[0]), "=r"((r)[1]), "=r"((r)[2]), "=r"((r)[3]) : "r"(addr))

#define MMA16816(c, a, b0, b1) \
    asm volatile("mma.sync.aligned.m16n8k16.row.col.f32.f16.f16.f32 " \
        "{%0,%1,%2,%3}, {%4,%5,%6,%7}, {%8,%9}, {%0,%1,%2,%3};" \
        : "+f"((c)[0]), "+f"((c)[1]), "+f"((c)[2]), "+f"((c)[3]) \
        : "r"((a)[0]), "r"((a)[1]), "r"((a)[2]), "r"((a)[3]), "r"(b0), "r"(b1))

#define STG_B 32768
#define SM_TOT (3*STG_B)

__device__ __forceinline__ int load_idx_i(const void* p, int i, int is64) {
    return is64 ? (int)((const long long*)p)[i] : ((const int*)p)[i];
}

// ---------------------------------------------------------------------------
// GEMM core (NT): acc += A[bm:bm+128, :K] * W[bn:bn+128, :K]^T
__device__ __forceinline__ void gemm_tile_core(
    float acc[2][8][4],
    const __half* __restrict__ Ab, int lda,
    const __half* __restrict__ Wb, int ldw,
    int KT, uint32_t sb, int tid,
    int gmode, const void* __restrict__ ts, int gbm, int is64)
{
    const int warp = tid >> 5, lane = tid & 31;
    const int wm = warp & 3, wn = warp >> 2;

    const __half* aptr[4];
    const __half* wptr[4];
    uint32_t soff[4];
    #pragma unroll
    for (int i = 0; i < 4; i++) {
        int c = tid + i * 256;
        int row = c >> 3, ch = c & 7;
        soff[i] = (uint32_t)((row << 7) + ((ch << 4) ^ ((row & 7) << 4)));
        if (gmode) {
            int m = gbm + row;
            int idx = load_idx_i(ts, m, is64);
            aptr[i] = Ab + (((size_t)(m >> 9) << 10) + (size_t)idx) * Dd + ch * 8;
        } else {
            aptr[i] = Ab + (size_t)row * lda + ch * 8;
        }
        wptr[i] = Wb + (size_t)row * ldw + ch * 8;
    }

    auto load = [&](int stage, int kt) {
        const int k0 = kt * 64;
        uint32_t sa = sb + stage * STG_B;
        uint32_t sw = sa + 16384;
        #pragma unroll
        for (int i = 0; i < 4; i++) {
            cp16(sa + soff[i], aptr[i] + k0);
            cp16(sw + soff[i], wptr[i] + k0);
        }
        CP_COMMIT();
    };

    load(0, 0);
    load(1, 1);

    const int rlA = (lane & 7) + ((lane >> 3) & 1) * 8;
    const int caA = ((lane >> 4) & 1) << 4;
    const int rlB = (lane & 7) + ((lane >> 4) & 1) * 8;
    const int caB = ((lane >> 3) & 1) << 4;
    const uint32_t swA = (uint32_t)(rlA & 7) << 4;
    const uint32_t swB = (uint32_t)(rlB & 7) << 4;
    const uint32_t rowA0 = (uint32_t)((wm * 32 +  0 + rlA) << 7);
    const uint32_t rowA1 = (uint32_t)((wm * 32 + 16 + rlA) << 7);
    const uint32_t rowB0 = (uint32_t)((wn * 64 +  0 + rlB) << 7);
    const uint32_t rowB1 = (uint32_t)((wn * 64 + 16 + rlB) << 7);
    const uint32_t rowB2 = (uint32_t)((wn * 64 + 32 + rlB) << 7);
    const uint32_t rowB3 = (uint32_t)((wn * 64 + 48 + rlB) << 7);

    for (int kt = 0; kt < KT; kt++) {
        if (kt + 2 < KT) { CP_WAIT(1); } else { CP_WAIT(0); }
        __syncthreads();
        if (kt + 2 < KT) load((kt + 2) % 3, kt + 2);

        uint32_t ab = sb + (kt % 3) * STG_B;
        uint32_t bb = ab + 16384;

        #pragma unroll
        for (int q = 0; q < 4; q++) {
            const uint32_t cA = (uint32_t)((q << 5) + caA) ^ swA;
            const uint32_t cB = (uint32_t)((q << 5) + caB) ^ swB;
            uint32_t a[2][4], b[4][4];
            LDSM4(a[0], ab + rowA0 + cA);
            LDSM4(a[1], ab + rowA1 + cA);
            LDSM4(b[0], bb + rowB0 + cB);
            LDSM4(b[1], bb + rowB1 + cB);
            LDSM4(b[2], bb + rowB2 + cB);
            LDSM4(b[3], bb + rowB3 + cB);
            #pragma unroll
            for (int mt = 0; mt < 2; mt++)
                #pragma unroll
                for (int np = 0; np < 4; np++) {
                    MMA16816(acc[mt][2*np],     a[mt], b[np][0], b[np][1]);
                    MMA16816(acc[mt][2*np + 1], a[mt], b[np][2], b[np][3]);
                }
        }
    }
}

// fp16 epilogue
__device__ __forceinline__ void epi_half(
    float acc[2][8][4], const float* __restrict__ bias, float alpha,
    __half* __restrict__ C, int ldc, int bm, int bn, int tid)
{
    const int warp = tid >> 5, lane = tid & 31;
    const int wm = warp & 3, wn = warp >> 2;
    const int g = lane >> 2, t2 = (lane & 3) * 2;
    #pragma unroll
    for (int nt = 0; nt < 8; nt++) {
        int c0 = bn + wn * 64 + nt * 8 + t2;
        float2 bv = *(const float2*)(bias + c0);
        #pragma unroll
        for (int mt = 0; mt < 2; mt++) {
            int r0 = bm + wm * 32 + mt * 16 + g;
            *(__half2*)(C + (size_t)r0 * ldc + c0) =
                __floats2half2_rn(alpha * (acc[mt][nt][0] + bv.x),
                                  alpha * (acc[mt][nt][1] + bv.y));
            *(__half2*)(C + (size_t)(r0 + 8) * ldc + c0) =
                __floats2half2_rn(alpha * (acc[mt][nt][2] + bv.x),
                                  alpha * (acc[mt][nt][3] + bv.y));
        }
    }
}

// ---------------------------------------------------------------------------
// mega GEMM launch: [0,64) Wc, [64,128) PE, [128,640) Q(gather),
// [640,1664) K, [1664,2688) V
__global__ __launch_bounds__(256, 2) void qkv_gemm(
    const float* __restrict__ bq, const float* __restrict__ bk,
    const float* __restrict__ bv, float qscale,
    const void* __restrict__ to_sem)
{
    extern __shared__ char smem[];
    const uint32_t sb = smem_u32(smem);
    const int tid = threadIdx.x;
    const int is64 = g_is64;
    int id = blockIdx.x;

    const __half* A; int lda;
    const __half* W; int ldw;
    const float* bias; __half* C;
    float alpha; int bm, bn, gmode, KT, seg;
    if (id < 64) {            // Wc = Wp1 @ Wo
        seg = 0; KT = 16; gmode = 0;
        bm = (id >> 3) * 128; bn = (id & 7) * 128;
        A = g_WPh + (size_t)bm * KFn; lda = KFn;
        W = g_WOTh + (size_t)bn * Dd; ldw = Dd;
        bias = g_zeros; C = g_Wch; alpha = 1.0f;
    } else if (id < 128) {    // PE = TE @ Wp2^T
        int t = id - 64;
        seg = 1; KT = 4; gmode = 0;
        bm = (t >> 3) * 128; bn = (t & 7) * 128;
        A = g_TEh + (size_t)bm * WDd; lda = WDd;
        W = g_WPh + (size_t)bn * KFn + Dd; ldw = KFn;
        bias = g_zeros; C = nullptr; alpha = 1.0f;
    } else if (id < 640) {    // Q (gathered A)
        int t = id - 128;
        seg = 2; KT = 16; gmode = 1;
        bm = (t >> 3) * 128; bn = (t & 7) * 128;
        A = g_ENCh; lda = Dd;
        W = g_WQh + (size_t)bn * Dd; ldw = Dd;
        bias = bq; C = g_Qh; alpha = qscale;
    } else if (id < 1664) {   // K
        int t = id - 640;
        seg = 2; KT = 16; gmode = 0;
        bm = (t >> 3) * 128; bn = (t & 7) * 128;
        A = g_ENCh + (size_t)bm * Dd; lda = Dd;
        W = g_WKh + (size_t)bn * Dd; ldw = Dd;
        bias = bk; C = g_Kh; alpha = 1.0f;
    } else {                  // V
        int t = id - 1664;
        seg = 2; KT = 16; gmode = 0;
        bm = (t >> 3) * 128; bn = (t & 7) * 128;
        A = g_ENCh + (size_t)bm * Dd; lda = Dd;
        W = g_WVh + (size_t)bn * Dd; ldw = Dd;
        bias = bv; C = g_Vh; alpha = 1.0f;
    }

    float acc[2][8][4];
    #pragma unroll
    for (int i = 0; i < 2; i++)
        #pragma unroll
        for (int j = 0; j < 8; j++)
            #pragma unroll
            for (int r = 0; r < 4; r++) acc[i][j][r] = 0.f;

    gemm_tile_core(acc, A, lda, W, ldw, KT, sb, tid, gmode, to_sem, bm, is64);

    if (seg == 1) {
        const int warp = tid >> 5, lane = tid & 31;
        const int wm = warp & 3, wn = warp >> 2;
        const int g = lane >> 2, t2 = (lane & 3) * 2;
        #pragma unroll
        for (int nt = 0; nt < 8; nt++) {
            int c0 = bn + wn * 64 + nt * 8 + t2;
            #pragma unroll
            for (int mt = 0; mt < 2; mt++) {
                int r0 = bm + wm * 32 + mt * 16 + g;
                float2 o0 = {acc[mt][nt][0], acc[mt][nt][1]};
                float2 o1 = {acc[mt][nt][2], acc[mt][nt][3]};
                *(float2*)(g_PE + (size_t)r0 * Dd + c0)       = o0;
                *(float2*)(g_PE + (size_t)(r0 + 8) * Dd + c0) = o1;
            }
        }
    } else {
        epi_half(acc, bias, alpha, C, Dd, bm, bn, tid);
    }
}

// combined projection: emb = CTXh @ Wch^T + bc + PE[tt]; dual store / EMB
__global__ __launch_bounds__(256, 2) void c_gemm(const void* __restrict__ tt,
                                                 float* __restrict__ out, int direct) {
    extern __shared__ char smem[];
    const uint32_t sb = smem_u32(smem);
    const int tid = threadIdx.x;
    int id = blockIdx.x;
    int bm = (id >> 3) * 128, bn = (id & 7) * 128;

    float acc[2][8][4];
    #pragma unroll
    for (int i = 0; i < 2; i++)
        #pragma unroll
        for (int j = 0; j < 8; j++)
            #pragma unroll
            for (int r = 0; r < 4; r++) acc[i][j][r] = 0.f;

    gemm_tile_core(acc, g_CTXh + (size_t)bm * Dd, Dd, g_Wch + (size_t)bn * Dd, Dd,
                   16, sb, tid, 0, nullptr, 0, 0);

    const int warp = tid >> 5, lane = tid & 31;
    const int wm = warp & 3, wn = warp >> 2;
    const int g = lane >> 2, t2 = (lane & 3) * 2;
    const int is64 = g_is64;

    int rows[2][2];
    const float* pe[2][2];
    #pragma unroll
    for (int mt = 0; mt < 2; mt++) {
        int r0 = bm + wm * 32 + mt * 16 + g;
        rows[mt][0] = r0;
        rows[mt][1] = r0 + 8;
        pe[mt][0] = g_PE + (size_t)load_idx_i(tt, r0,     is64) * Dd;
        pe[mt][1] = g_PE + (size_t)load_idx_i(tt, r0 + 8, is64) * Dd;
    }

    #pragma unroll
    for (int nt = 0; nt < 8; nt++) {
        int c0 = bn + wn * 64 + nt * 8 + t2;
        float2 bv = *(const float2*)(g_bc + c0);
        #pragma unroll
        for (int mt = 0; mt < 2; mt++) {
            float2 pa = *(const float2*)(pe[mt][0] + c0);
            float2 pb = *(const float2*)(pe[mt][1] + c0);
            int r0 = rows[mt][0], rb = rows[mt][1];
            float2 o0 = {acc[mt][nt][0] + bv.x + pa.x, acc[mt][nt][1] + bv.y + pa.y};
            float2 o1 = {acc[mt][nt][2] + bv.x + pb.x, acc[mt][nt][3] + bv.y + pb.y};
            if (direct) {
                int b0 = r0 >> 9, l0 = r0 & 511;
                int b1 = rb >> 9, l1 = rb & 511;
                *(float2*)(out + (size_t)r0 * Dd + c0) = o0;
                *(float2*)(out + (size_t)rb * Dd + c0) = o1;
                *(float2*)(out + T1c + ((size_t)b0 * (Ls+1) + l0 + 1) * Dd + c0) = o0;
                *(float2*)(out + T1c + ((size_t)b1 * (Ls+1) + l1 + 1) * Dd + c0) = o1;
            } else {
                *(float2*)(g_EMB + (size_t)r0 * Dd + c0) = o0;
                *(float2*)(g_EMB + (size_t)rb * Dd + c0) = o1;
            }
        }
    }
}

// ---------------------------------------------------------------------------
// fp32 -> fp16 conversions + dtype detect (seg 7); seg 4 unused (Wo in prep)
__global__ void f2h_all(const float* __restrict__ e, const float* __restrict__ q,
                        const float* __restrict__ k, const float* __restrict__ v,
                        const float* __restrict__ o, const float* __restrict__ p,
                        const float* __restrict__ te,
                        const void* __restrict__ to_sem) {
    int seg = blockIdx.y;
    if (seg == 7) {
        __shared__ int nz;
        if (threadIdx.x == 0) nz = 0;
        __syncthreads();
        if (blockIdx.x == 0) {
            const int* qw = (const int*)to_sem;
            int bad = 0;
            for (int i = threadIdx.x * 2 + 1; i < 8192; i += 2 * blockDim.x)
                if (qw[i] != 0) bad = 1;
            if (bad) atomicAdd(&nz, 1);
            __syncthreads();
            if (threadIdx.x == 0) g_is64 = (nz == 0) ? 1 : 0;
        }
        return;
    }
    if (seg == 4) return;
    const float* srcs[7] = {e, q, k, v, o, p, te};
    __half* dsts[7] = {g_ENCh, g_WQh, g_WKh, g_WVh, nullptr, g_WPh, g_TEh};
    const int n8s[7] = {BSn*Dd/8, Dd*Dd/8, Dd*Dd/8, Dd*Dd/8, 0, Dd*KFn/8,
                        VOCP*WDd/8};
    const int vr8 = VOCR*WDd/8;
    const float* src = srcs[seg];
    __half* dst = dsts[seg];
    int n8 = n8s[seg];
    for (int i = blockIdx.x * blockDim.x + threadIdx.x; i < n8;
         i += gridDim.x * blockDim.x) {
        float4 a, b;
        if (seg == 6 && i >= vr8) {
            a = make_float4(0.f, 0.f, 0.f, 0.f);
            b = a;
        } else {
            a = ((const float4*)src)[2*i];
            b = ((const float4*)src)[2*i+1];
        }
        __half2 h[4];
        h[0] = __floats2half2_rn(a.x, a.y);
        h[1] = __floats2half2_rn(a.z, a.w);
        h[2] = __floats2half2_rn(b.x, b.y);
        h[3] = __floats2half2_rn(b.z, b.w);
        ((float4*)dst)[i] = *(float4*)h;
    }
}

// ---------------------------------------------------------------------------
// prep kernel: [0,1024) Wo transpose; [1024,2048) bc; [2048,2064) buckets;
// [2064,2080) root rows
__global__ __launch_bounds__(256) void prep(
    const float* __restrict__ wo, const float* __restrict__ wp,
    const float* __restrict__ bo, const float* __restrict__ bp,
    const void* __restrict__ sem_syn,
    const float* __restrict__ root, float* __restrict__ out, int direct)
{
    int id = blockIdx.x;
    int tid = threadIdx.x;

    if (id < 1024) {
        __shared__ float t[32][33];
        int bx = (id & 31) * 32, by = (id >> 5) * 32;
        int x = tid & 31, y0 = tid >> 5;
        #pragma unroll
        for (int dy = 0; dy < 32; dy += 8)
            t[y0 + dy][x] = wo[(size_t)(by + y0 + dy) * Dd + bx + x];
        __syncthreads();
        #pragma unroll
        for (int dy = 0; dy < 32; dy += 8) {
            int i = bx + y0 + dy;
            int j = by + x;
            g_WOTh[(size_t)i * Dd + j] = __float2half(t[x][y0 + dy]);
        }
        return;
    }
    if (id < 2048) {
        __shared__ float wsum[8];
        int n = id - 1024;
        const float* row = wp + (size_t)n * KFn;
        float s = 0.f;
        for (int k = tid * 2; k < Dd; k += 512) {
            float2 a = *(const float2*)(row + k);
            float2 b = *(const float2*)(bo + k);
            s += a.x * b.x + a.y * b.y;
        }
        s += __shfl_xor_sync(0xffffffffu, s, 1);
        s += __shfl_xor_sync(0xffffffffu, s, 2);
        s += __shfl_xor_sync(0xffffffffu, s, 4);
        s += __shfl_xor_sync(0xffffffffu, s, 8);
        s += __shfl_xor_sync(0xffffffffu, s, 16);
        if ((tid & 31) == 0) wsum[tid >> 5] = s;
        __syncthreads();
        if (tid == 0) {
            float tot = bp[n];
            #pragma unroll
            for (int w = 0; w < 8; w++) tot += wsum[w];
            g_bc[n] = tot;
        }
        return;
    }
    if (id < 2048 + Bz) {
        int b = id - 2048;
        const int is64 = g_is64;
        for (int j = tid; j < Ls; j += 256) g_bcnt[b * Ls + j] = 0;
        __syncthreads();
        for (int it = 0; it < 4; it++) {
            int j = it * 256 + tid;
            long long v = is64 ? ((const long long*)sem_syn)[b * Ss + j]
                               : (long long)((const int*)sem_syn)[b * Ss + j];
            if (v >= 1 && v <= Ls) {
                int i = (int)v - 1;
                int slot = atomicAdd(&g_bcnt[b * Ls + i], 1);
                if (slot < BKT) g_bkt[(b * Ls + i) * BKT + slot] = (unsigned short)j;
            }
        }
        return;
    }
    if (direct) {
        int b = id - 2048 - Bz;
        ((float4*)(out + (size_t)T1c + (size_t)b * (Ls + 1) * Dd))[tid] =
            ((const float4*)root)[tid];
    }
}

// ---------------------------------------------------------------------------
// Sparse masked attention; register-prefetched K/V row batches (MLP = M).
#define PF 8
__global__ __launch_bounds__(128) void attn_kernel(
    const void* __restrict__ to_sem, const void* __restrict__ sem_syn)
{
    int bl = blockIdx.x;
    int b = bl >> 9, i = bl & 511;
    int tid = threadIdx.x;

    __shared__ int   s_idx[BKT + 8];
    __shared__ float s_sc[Hh][BKT + 8];
    __shared__ int   s_total;

    const int is64 = g_is64;
    const int base = b * Ss;
    const long long target = (long long)(i + 1);

    int cnt = g_bcnt[bl];
    if (cnt > BKT) cnt = BKT;
    if (tid < cnt) s_idx[tid] = g_bkt[bl * BKT + tid];
    __syncthreads();

    if (tid == 0) {
        for (int x = 1; x < cnt; x++) {
            int key = s_idx[x];
            int y = x - 1;
            while (y >= 0 && s_idx[y] > key) { s_idx[y + 1] = s_idx[y]; y--; }
            s_idx[y + 1] = key;
        }
        int jself = load_idx_i(to_sem, bl, is64);
        long long vs = is64 ? ((const long long*)sem_syn)[base + jself]
                            : (long long)((const int*)sem_syn)[base + jself];
        int M = cnt;
        if (vs != target) { s_idx[M] = jself; M++; }
        s_total = M;
    }
    __syncthreads();
    const int M = s_total;
    const int MP = (M < PF) ? M : PF;

    int h = tid >> 4, l16 = tid & 15;
    const size_t lofs = (size_t)h * DHd + l16 * 8;
    float qr[8];
    {
        uint4 u = *(const uint4*)(g_Qh + (size_t)bl * Dd + lofs);
        const __half2* hp = (const __half2*)&u;
        float2 f0 = __half22float2(hp[0]), f1 = __half22float2(hp[1]);
        float2 f2 = __half22float2(hp[2]), f3 = __half22float2(hp[3]);
        qr[0]=f0.x; qr[1]=f0.y; qr[2]=f1.x; qr[3]=f1.y;
        qr[4]=f2.x; qr[5]=f2.y; qr[6]=f3.x; qr[7]=f3.y;
    }

    // ---- scores: batch-prefetch K rows (independent loads -> MLP=M) ----
    {
        uint4 kv[PF];
        #pragma unroll
        for (int m = 0; m < PF; m++)
            if (m < MP)
                kv[m] = *(const uint4*)(g_Kh + (size_t)(base + s_idx[m]) * Dd + lofs);

        auto score = [&](uint4 u, int m) {
            const __half2* hp = (const __half2*)&u;
            float2 k0 = __half22float2(hp[0]), k1 = __half22float2(hp[1]);
            float2 k2 = __half22float2(hp[2]), k3 = __half22float2(hp[3]);
            float p = qr[0]*k0.x + qr[1]*k0.y + qr[2]*k1.x + qr[3]*k1.y
                    + qr[4]*k2.x + qr[5]*k2.y + qr[6]*k3.x + qr[7]*k3.y;
            p += __shfl_xor_sync(0xffffffffu, p, 1);
            p += __shfl_xor_sync(0xffffffffu, p, 2);
            p += __shfl_xor_sync(0xffffffffu, p, 4);
            p += __shfl_xor_sync(0xffffffffu, p, 8);
            if (l16 == 0) s_sc[h][m] = p;
        };

        #pragma unroll
        for (int m = 0; m < PF; m++)
            if (m < MP) score(kv[m], m);
        for (int m = PF; m < M; m++) {
            uint4 u = *(const uint4*)(g_Kh + (size_t)(base + s_idx[m]) * Dd + lofs);
            score(u, m);
        }
    }
    __syncthreads();

    float mx = -3.0e38f;
    for (int m = 0; m < M; m++) mx = fmaxf(mx, s_sc[h][m]);
    float den = 0.f;
    for (int m = 0; m < M; m++) den += expf(s_sc[h][m] - mx);

    // ---- context: batch-prefetch V rows ----
    float acc[8];
    #pragma unroll
    for (int c = 0; c < 8; c++) acc[c] = 0.f;
    {
        uint4 vv[PF];
        #pragma unroll
        for (int m = 0; m < PF; m++)
            if (m < MP)
                vv[m] = *(const uint4*)(g_Vh + (size_t)(base + s_idx[m]) * Dd + lofs);

        auto accum = [&](uint4 u, int m) {
            float p = expf(s_sc[h][m] - mx);
            const __half2* hp = (const __half2*)&u;
            float2 v0 = __half22float2(hp[0]), v1 = __half22float2(hp[1]);
            float2 v2 = __half22float2(hp[2]), v3 = __half22float2(hp[3]);
            acc[0] += p * v0.x; acc[1] += p * v0.y; acc[2] += p * v1.x; acc[3] += p * v1.y;
            acc[4] += p * v2.x; acc[5] += p * v2.y; acc[6] += p * v3.x; acc[7] += p * v3.y;
        };

        #pragma unroll
        for (int m = 0; m < PF; m++)
            if (m < MP) accum(vv[m], m);
        for (int m = PF; m < M; m++) {
            uint4 u = *(const uint4*)(g_Vh + (size_t)(base + s_idx[m]) * Dd + lofs);
            accum(u, m);
        }
    }
    float inv = 1.0f / den;
    __half2 h0 = __floats2half2_rn(acc[0]*inv, acc[1]*inv);
    __half2 h1 = __floats2half2_rn(acc[2]*inv, acc[3]*inv);
    __half2 h2 = __floats2half2_rn(acc[4]*inv, acc[5]*inv);
    __half2 h3 = __floats2half2_rn(acc[6]*inv, acc[7]*inv);
    uint4 u = { *(uint32_t*)&h0, *(uint32_t*)&h1, *(uint32_t*)&h2, *(uint32_t*)&h3 };
    *(uint4*)(g_CTXh + (size_t)bl * Dd + lofs) = u;
}

// ---------------------------------------------------------------------------
// fallback output packer (only used when out_size doesn't match full tuple)
__global__ void write_out(const float* __restrict__ root, float* __restrict__ out,
                          int out_size) {
    const int T1 = T1c, T2 = T2c;
    int base2, n;
    if (out_size >= T1 + T2)      { base2 = T1; n = T1 + T2; }
    else if (out_size == T2)      { base2 = 0;  n = T2; }
    else                          { base2 = -1; n = T1; }
    int n4 = n >> 2;
    for (int i4 = blockIdx.x * blockDim.x + threadIdx.x; i4 < n4;
         i4 += gridDim.x * blockDim.x) {
        int e = i4 << 2;
        float4 val;
        if (base2 >= 0 && e >= base2) {
            int off = e - base2;
            int b = off / ((Ls + 1) * Dd);
            int r = off - b * ((Ls + 1) * Dd);
            int l = r >> 10;
            int dd = r & (Dd - 1);
            if (l == 0)
                val = ((const float4*)root)[dd >> 2];
            else
                val = ((const float4*)(g_EMB + ((size_t)(b * Ls + l - 1) << 10)))[dd >> 2];
        } else {
            val = ((const float4*)g_EMB)[i4];
        }
        ((float4*)out)[i4] = val;
    }
}

// ---------------------------------------------------------------------------
extern "C" void kernel_launch(void* const* d_in, const int* in_sizes, int n_in,
                              void* d_out, int out_size) {
    const float* enc     = (const float*)d_in[0];
    const void*  to_sem  = d_in[1];
    const void*  tt      = d_in[2];
    const void*  sem_syn = d_in[3];
    const float* bq = (const float*)d_in[5];
    const float* bk = (const float*)d_in[7];
    const float* bv = (const float*)d_in[9];
    const float* wo = (const float*)d_in[10];
    const float* bo = (const float*)d_in[11];
    const float* type_emb = (const float*)d_in[12];
    const float* w_proj   = (const float*)d_in[13];
    const float* b_proj   = (const float*)d_in[14];
    const float* root     = (const float*)d_in[15];

    cudaFuncSetAttribute(qkv_gemm, cudaFuncAttributeMaxDynamicSharedMemorySize, SM_TOT);
    cudaFuncSetAttribute(c_gemm,   cudaFuncAttributeMaxDynamicSharedMemorySize, SM_TOT);

    const float qscale = 0.08838834764831843f;   // 1/sqrt(128)
    const int direct = (out_size >= T1c + T2c);

    f2h_all<<<dim3(1024, 8), 256>>>(enc, (const float*)d_in[4], (const float*)d_in[6],
                                    (const float*)d_in[8], wo,
                                    w_proj, type_emb, to_sem);
    prep<<<2048 + 2 * Bz, 256>>>(wo, w_proj, bo, b_proj, sem_syn,
                                 root, (float*)d_out, direct);

    qkv_gemm<<<2688, 256, SM_TOT>>>(bq, bk, bv, qscale, to_sem);

    attn_kernel<<<BLn, 128>>>(to_sem, sem_syn);

    c_gemm<<<512, 256, SM_TOT>>>(tt, (float*)d_out, direct);

    if (!direct) write_out<<<2048, 256>>>(root, (float*)d_out, out_size);
}